// round 1
// baseline (speedup 1.0000x reference)
#include <cuda_runtime.h>

// ---------------------------------------------------------------------------
// Problem: u[i] = 0.25*k*dy * sum_j Y1(k*r_ij) * (diff.n_j)/(r_ij+eps) * h_j
// with h_j = MLP(boundary_j).  Boundary = 4 sides of unit square, so per side
// diff.n is constant per query: c_s, and r^2 = (u - cord_j)^2 + c_s^2.
// ---------------------------------------------------------------------------

#define MAXM 4096
#define MAXH 64

// scratch (no allocations allowed)
__device__ float  g_buf1[MAXM * MAXH];
__device__ float  g_buf2[MAXM * MAXH];
__device__ float2 g_bh[MAXM];   // {cord_j, h_j}

// ------------------------------ MLP prep -----------------------------------

__global__ void mlp_l1_kernel(const float* __restrict__ bp,
                              const float* __restrict__ W1,
                              const float* __restrict__ b1,
                              int M, int H) {
    int idx = blockIdx.x * blockDim.x + threadIdx.x;
    if (idx >= M * H) return;
    int i = idx / H, j = idx - i * H;
    float v = fmaf(bp[2 * i + 1], W1[H + j], b1[j]);
    v = fmaf(bp[2 * i], W1[j], v);
    g_buf1[idx] = tanhf(v);
}

// dir==0: g_buf1 -> g_buf2 ; dir==1: g_buf2 -> g_buf1
__global__ void mlp_mid_kernel(const float* __restrict__ W,
                               const float* __restrict__ b,
                               int M, int H, int dir) {
    int idx = blockIdx.x * blockDim.x + threadIdx.x;
    if (idx >= M * H) return;
    int i = idx / H, j = idx - i * H;
    const float* in  = dir ? g_buf2 : g_buf1;
    float*       out = dir ? g_buf1 : g_buf2;
    float acc = b[j];
    const float* row = in + i * H;
    for (int k = 0; k < H; ++k)
        acc = fmaf(row[k], W[k * H + j], acc);
    out[idx] = tanhf(acc);
}

// reads g_buf2 (after L1->buf2, buf2->buf1, buf1->buf2 ... sequence below)
__global__ void mlp_out_kernel(const float* __restrict__ W5,
                               const float* __restrict__ b5,
                               const float* __restrict__ bp,
                               int M, int H, int Nside, int src) {
    int i = blockIdx.x * blockDim.x + threadIdx.x;
    if (i >= M) return;
    const float* in = src ? g_buf2 : g_buf1;
    float acc = b5[0];
    const float* row = in + i * H;
    for (int k = 0; k < H; ++k)
        acc = fmaf(row[k], W5[k], acc);
    int side = i / Nside;
    // top/bottom boundary points: (cord, const_y) -> u coord is x (bp[2i])
    // left/right:                 (const_x, cord) -> u coord is y (bp[2i+1])
    float u = (side < 2) ? bp[2 * i] : bp[2 * i + 1];
    g_bh[i] = make_float2(u, acc);
}

// ------------------------------ Y1 evaluation -------------------------------
// Numerical-Recipes Y1, mirrored exactly from the reference (fp32, like jax).
// x = 15*r, invr = 1/r  (so 1/x = invr/15, 8/x = (8/15)*invr).
__device__ __forceinline__ float y1_eval(float x, float invr) {
    if (x < 8.0f) {
        float y = x * x;
        float jn = fmaf(y, -30.16036606f, 15704.48260f);
        jn = fmaf(y, jn, -2972611.439f);
        jn = fmaf(y, jn, 242396853.1f);
        jn = fmaf(y, jn, -7895059235.0f);
        jn = fmaf(y, jn, 72362614232.0f);
        jn *= x;
        float jd = y + 376.9991397f;
        jd = fmaf(y, jd, 99447.43394f);
        jd = fmaf(y, jd, 18583304.74f);
        jd = fmaf(y, jd, 2300535178.0f);
        jd = fmaf(y, jd, 144725228442.0f);
        float yn = fmaf(y, 8.511937935e4f, -4.237922726e7f);
        yn = fmaf(y, yn, 7.349264551e9f);
        yn = fmaf(y, yn, -5.153438139e11f);
        yn = fmaf(y, yn, 1.275274390e13f);
        yn = fmaf(y, yn, -4.900604943e13f);
        yn *= x;
        float yd = y + 3.549632885e3f;
        yd = fmaf(y, yd, 1.020426050e6f);
        yd = fmaf(y, yd, 2.245904002e8f);
        yd = fmaf(y, yd, 3.733650367e10f);
        yd = fmaf(y, yd, 4.244419664e12f);
        yd = fmaf(y, yd, 2.499580570e14f);
        // one reciprocal serves both rationals
        float rden = __fdividef(1.0f, jd * yd);
        float j1 = jn * yd * rden;
        float ys = yn * jd * rden;
        float lg = __logf(x);
        float invx = invr * (1.0f / 15.0f);
        return fmaf(0.636619772f, fmaf(j1, lg, -invx), ys);
    } else {
        float z = (8.0f / 15.0f) * invr;         // 8/x
        float y2 = z * z;
        float xx = x - 2.356194491f;
        float p1 = fmaf(y2, -0.240337019e-6f, 0.2457520174e-5f);
        p1 = fmaf(y2, p1, -0.3516396496e-4f);
        p1 = fmaf(y2, p1, 0.183105e-2f);
        p1 = fmaf(y2, p1, 1.0f);
        float p2 = fmaf(y2, 0.105787412e-6f, -0.88228987e-6f);
        p2 = fmaf(y2, p2, 0.8449199096e-5f);
        p2 = fmaf(y2, p2, -0.2002690873e-3f);
        p2 = fmaf(y2, p2, 0.04687499995f);
        float amp = rsqrtf(x * 1.5707963268f);   // sqrt(0.636619772/x)
        float s, c;
        __sincosf(xx, &s, &c);
        return amp * fmaf(z, c * p2, s * p1);
    }
}

// ------------------------------ main kernel ---------------------------------
// One warp per query point; lanes stride over boundary points of each side.
// Adjacent lanes hit adjacent cords -> warp-coherent small/large branch.
__global__ void __launch_bounds__(128) bem_main_kernel(
        const float* __restrict__ points,
        const float* __restrict__ dyp,
        float* __restrict__ out,
        int P, int Nside) {
    int gwarp = (blockIdx.x * blockDim.x + threadIdx.x) >> 5;
    int lane = threadIdx.x & 31;
    if (gwarp >= P) return;
    float px = points[2 * gwarp];
    float py = points[2 * gwarp + 1];

    // per-side signed normal distance c_s = diff . n  (constant over the side)
    float c0 = py - 1.0f;   // top    n=(0, 1)
    float c1 = -py;         // bottom n=(0,-1)
    float c2 = -px;         // left   n=(-1,0)
    float c3 = px - 1.0f;   // right  n=(1, 0)

    float part = 0.0f;
    #pragma unroll
    for (int s = 0; s < 4; ++s) {
        float c = (s == 0) ? c0 : (s == 1) ? c1 : (s == 2) ? c2 : c3;
        float u = (s < 2) ? px : py;
        float d2 = c * c;
        const float2* B = g_bh + s * Nside;
        float acc = 0.0f;
        int iters = (Nside + 31) >> 5;
        #pragma unroll 2
        for (int it = 0; it < iters; ++it) {
            int j = (it << 5) + lane;
            if (j < Nside) {
                float2 v = B[j];                    // {cord, h}
                float du = u - v.x;
                float r2 = fmaf(du, du, d2);
                r2 = fmaxf(r2, 1e-24f);             // guard exact coincidence
                float invr = rsqrtf(r2);            // 1/r
                float r = r2 * invr;
                float x = 15.0f * r;
                float invre = __fdividef(1.0f, r + 1e-8f);
                float y1 = y1_eval(x, invr);
                acc = fmaf(y1, v.y * invre, acc);
            }
        }
        part = fmaf(c, acc, part);
    }
    // deterministic warp reduction
    #pragma unroll
    for (int o = 16; o > 0; o >>= 1)
        part += __shfl_down_sync(0xffffffffu, part, o);
    if (lane == 0)
        out[gwarp] = 0.25f * 15.0f * dyp[0] * part;
}

// ------------------------------ launch --------------------------------------

extern "C" void kernel_launch(void* const* d_in, const int* in_sizes, int n_in,
                              void* d_out, int out_size) {
    const float* points = (const float*)d_in[0];
    const float* bp     = (const float*)d_in[1];
    // d_in[2] = normals (unused: side structure supplies them exactly)
    const float* dy     = (const float*)d_in[3];
    const float* W1 = (const float*)d_in[4];
    const float* b1 = (const float*)d_in[5];
    const float* W2 = (const float*)d_in[6];
    const float* b2 = (const float*)d_in[7];
    const float* W3 = (const float*)d_in[8];
    const float* b3 = (const float*)d_in[9];
    const float* W4 = (const float*)d_in[10];
    const float* b4 = (const float*)d_in[11];
    const float* W5 = (const float*)d_in[12];
    const float* b5 = (const float*)d_in[13];

    int P = in_sizes[0] / 2;
    int M = in_sizes[1] / 2;
    int H = in_sizes[5];
    int Nside = M / 4;

    int nh = M * H;
    int tb = 256;
    int gh = (nh + tb - 1) / tb;

    // MLP: L1 -> buf1 ; L2: buf1->buf2 ; L3: buf2->buf1 ; L4: buf1->buf2
    mlp_l1_kernel<<<gh, tb>>>(bp, W1, b1, M, H);
    mlp_mid_kernel<<<gh, tb>>>(W2, b2, M, H, 0);   // buf1 -> buf2
    mlp_mid_kernel<<<gh, tb>>>(W3, b3, M, H, 1);   // buf2 -> buf1
    mlp_mid_kernel<<<gh, tb>>>(W4, b4, M, H, 0);   // buf1 -> buf2
    mlp_out_kernel<<<(M + tb - 1) / tb, tb>>>(W5, b5, bp, M, H, Nside, 1); // reads buf2

    // main: one warp per query point
    long long total = (long long)P * 32;
    int mb = 128;
    int mg = (int)((total + mb - 1) / mb);
    bem_main_kernel<<<mg, mb>>>(points, dy, (float*)d_out, P, Nside);
}

// round 2
// speedup vs baseline: 1.2218x; 1.2218x over previous
#include <cuda_runtime.h>

// ---------------------------------------------------------------------------
// u[i] = 0.25*k*dy * sum_j Y1(k*r_ij) * (diff.n_j)/(r_ij+eps) * h_j
// Boundary = 4 sides of unit square on a uniform cord grid:
//   per side: diff.n = c_s (const per query), r^2 = (u-cord_j)^2 + c_s^2
//   small/large Bessel branch <=> cord_j in a contiguous interval (analytic!)
// ---------------------------------------------------------------------------

#define MAXM 4096
#define MAXH 64

// scratch (no allocations allowed)
__device__ float  g_buf1[MAXM * MAXH];
__device__ float  g_buf2[MAXM * MAXH];
__device__ __align__(16) float g_cord[MAXM];
__device__ __align__(16) float g_h[MAXM];

// ========================= packed f32x2 helpers =============================
typedef unsigned long long u64t;

__device__ __forceinline__ u64t F2(float a, float b) {
    u64t r; asm("mov.b64 %0,{%1,%2};" : "=l"(r) : "f"(a), "f"(b)); return r;
}
__device__ __forceinline__ u64t F2c(float a) { return F2(a, a); }
__device__ __forceinline__ void UPK(u64t v, float& a, float& b) {
    asm("mov.b64 {%0,%1},%2;" : "=f"(a), "=f"(b) : "l"(v));
}
__device__ __forceinline__ u64t FMA2(u64t a, u64t b, u64t c) {
    u64t d; asm("fma.rn.f32x2 %0,%1,%2,%3;" : "=l"(d) : "l"(a), "l"(b), "l"(c)); return d;
}
__device__ __forceinline__ u64t MUL2(u64t a, u64t b) {
    u64t d; asm("mul.rn.f32x2 %0,%1,%2;" : "=l"(d) : "l"(a), "l"(b)); return d;
}
__device__ __forceinline__ u64t ADD2(u64t a, u64t b) {
    u64t d; asm("add.rn.f32x2 %0,%1,%2;" : "=l"(d) : "l"(a), "l"(b)); return d;
}
__device__ __forceinline__ float rcpf(float x) {
    float r; asm("rcp.approx.f32 %0,%1;" : "=f"(r) : "f"(x)); return r;
}

// ========================= fused MLP (H == 50) ==============================
#define HID 50
#define PTS_PER_BLK 32

__global__ void __launch_bounds__(256) mlp_fused_kernel(
        const float* __restrict__ bp,
        const float* __restrict__ W1, const float* __restrict__ b1,
        const float* __restrict__ W2, const float* __restrict__ b2,
        const float* __restrict__ W3, const float* __restrict__ b3,
        const float* __restrict__ W4, const float* __restrict__ b4,
        const float* __restrict__ W5, const float* __restrict__ b5,
        int Nside) {
    __shared__ float sW2[HID * HID], sW3[HID * HID], sW4[HID * HID];
    __shared__ float sW1[2 * HID], sW5[HID];
    __shared__ float sb1[HID], sb2[HID], sb3[HID], sb4[HID];
    __shared__ float sA[PTS_PER_BLK][HID], sB[PTS_PER_BLK][HID];

    int tid = threadIdx.x;
    for (int i = tid; i < HID * HID; i += 256) {
        sW2[i] = W2[i]; sW3[i] = W3[i]; sW4[i] = W4[i];
    }
    if (tid < 2 * HID) sW1[tid] = W1[tid];
    if (tid < HID) {
        sW5[tid] = W5[tid];
        sb1[tid] = b1[tid]; sb2[tid] = b2[tid];
        sb3[tid] = b3[tid]; sb4[tid] = b4[tid];
    }
    int p0 = blockIdx.x * PTS_PER_BLK;
    __syncthreads();

    // L1: input -> sA
    for (int t = tid; t < PTS_PER_BLK * HID; t += 256) {
        int i = t / HID, j = t - i * HID;
        int gi = p0 + i;
        float x0 = bp[2 * gi], x1 = bp[2 * gi + 1];
        sA[i][j] = tanhf(fmaf(x0, sW1[j], fmaf(x1, sW1[HID + j], sb1[j])));
    }
    __syncthreads();
    // L2: sA -> sB
    for (int t = tid; t < PTS_PER_BLK * HID; t += 256) {
        int i = t / HID, j = t - i * HID;
        float acc = sb2[j];
        #pragma unroll
        for (int k = 0; k < HID; ++k) acc = fmaf(sA[i][k], sW2[k * HID + j], acc);
        sB[i][j] = tanhf(acc);
    }
    __syncthreads();
    // L3: sB -> sA
    for (int t = tid; t < PTS_PER_BLK * HID; t += 256) {
        int i = t / HID, j = t - i * HID;
        float acc = sb3[j];
        #pragma unroll
        for (int k = 0; k < HID; ++k) acc = fmaf(sB[i][k], sW3[k * HID + j], acc);
        sA[i][j] = tanhf(acc);
    }
    __syncthreads();
    // L4: sA -> sB
    for (int t = tid; t < PTS_PER_BLK * HID; t += 256) {
        int i = t / HID, j = t - i * HID;
        float acc = sb4[j];
        #pragma unroll
        for (int k = 0; k < HID; ++k) acc = fmaf(sA[i][k], sW4[k * HID + j], acc);
        sB[i][j] = tanhf(acc);
    }
    __syncthreads();
    // output + SoA store {cord, h}
    for (int i = tid; i < PTS_PER_BLK; i += 256) {
        int gi = p0 + i;
        float acc = b5[0];
        #pragma unroll
        for (int k = 0; k < HID; ++k) acc = fmaf(sB[i][k], sW5[k], acc);
        int side = gi / Nside;
        float u = (side < 2) ? bp[2 * gi] : bp[2 * gi + 1];
        g_cord[gi] = u;
        g_h[gi] = acc;
    }
}

// ===================== fallback layered MLP (H != 50) =======================
__global__ void mlp_l1_kernel(const float* __restrict__ bp,
                              const float* __restrict__ W1,
                              const float* __restrict__ b1, int M, int H) {
    int idx = blockIdx.x * blockDim.x + threadIdx.x;
    if (idx >= M * H) return;
    int i = idx / H, j = idx - i * H;
    float v = fmaf(bp[2 * i + 1], W1[H + j], b1[j]);
    v = fmaf(bp[2 * i], W1[j], v);
    g_buf1[idx] = tanhf(v);
}
__global__ void mlp_mid_kernel(const float* __restrict__ W,
                               const float* __restrict__ b, int M, int H, int dir) {
    int idx = blockIdx.x * blockDim.x + threadIdx.x;
    if (idx >= M * H) return;
    int i = idx / H, j = idx - i * H;
    const float* in  = dir ? g_buf2 : g_buf1;
    float*       out = dir ? g_buf1 : g_buf2;
    float acc = b[j];
    const float* row = in + i * H;
    for (int k = 0; k < H; ++k) acc = fmaf(row[k], W[k * H + j], acc);
    out[idx] = tanhf(acc);
}
__global__ void mlp_out_kernel(const float* __restrict__ W5,
                               const float* __restrict__ b5,
                               const float* __restrict__ bp,
                               int M, int H, int Nside, int src) {
    int i = blockIdx.x * blockDim.x + threadIdx.x;
    if (i >= M) return;
    const float* in = src ? g_buf2 : g_buf1;
    float acc = b5[0];
    const float* row = in + i * H;
    for (int k = 0; k < H; ++k) acc = fmaf(row[k], W5[k], acc);
    int side = i / Nside;
    float u = (side < 2) ? bp[2 * i] : bp[2 * i + 1];
    g_cord[i] = u;
    g_h[i] = acc;
}

// ===================== packed branch-free segment bodies ====================
// LARGE branch (x = 15 r >= 8): Y1 ~ sqrt(.6366/x)*(sin(xx)p1 + z cos(xx)p2)
__device__ __forceinline__ u64t seg_large(const float* __restrict__ gc,
                                          const float* __restrict__ gh,
                                          int lo, int hi, int lane,
                                          float u, float d2, u64t acc) {
    u64t nup  = F2c(-u), d2p = F2c(d2);
    u64t k15  = F2c(15.0f), mphi = F2c(-2.356194491f);
    u64t c815 = F2c(0.5333333333f);       // 8/15
    u64t cq   = F2c(23.5619449019f);      // 15 * pi/2  -> amp = rsqrt(cq * r)
    u64t A4 = F2c(-0.240337019e-6f), A3 = F2c(0.2457520174e-5f);
    u64t A2 = F2c(-0.3516396496e-4f), A1 = F2c(0.183105e-2f), A0 = F2c(1.0f);
    u64t B4 = F2c(0.105787412e-6f), B3 = F2c(-0.88228987e-6f);
    u64t B2 = F2c(0.8449199096e-5f), B1 = F2c(-0.2002690873e-3f);
    u64t B0 = F2c(0.04687499995f);
    u64t epsn = F2c(-1e-8f);

    #pragma unroll 2
    for (int j = lo + 2 * lane; j < hi; j += 64) {
        u64t cp = *(const u64t*)(gc + j);
        u64t hp = *(const u64t*)(gh + j);
        u64t dup = ADD2(cp, nup);                  // cord - u (sign irrelevant)
        u64t r2p = FMA2(dup, dup, d2p);
        float r20, r21; UPK(r2p, r20, r21);
        float i0 = rsqrtf(r20), i1 = rsqrtf(r21);
        u64t ip = F2(i0, i1);
        u64t rp = MUL2(r2p, ip);                   // r
        u64t xxp = FMA2(k15, rp, mphi);            // 15r - 3pi/4
        u64t zp = MUL2(c815, ip);                  // 8/x
        u64t y2p = MUL2(zp, zp);
        u64t p1 = FMA2(y2p, A4, A3);
        p1 = FMA2(y2p, p1, A2); p1 = FMA2(y2p, p1, A1); p1 = FMA2(y2p, p1, A0);
        u64t p2 = FMA2(y2p, B4, B3);
        p2 = FMA2(y2p, p2, B2); p2 = FMA2(y2p, p2, B1); p2 = FMA2(y2p, p2, B0);
        u64t qp = MUL2(cq, rp);
        float q0, q1; UPK(qp, q0, q1);
        float a0 = rsqrtf(q0), a1 = rsqrtf(q1);    // sqrt(0.6366/x)
        float xx0, xx1; UPK(xxp, xx0, xx1);
        float s0 = __sinf(xx0), s1 = __sinf(xx1);
        float co0 = __cosf(xx0), co1 = __cosf(xx1);
        u64t sp = F2(s0, s1), cop = F2(co0, co1), ap = F2(a0, a1);
        u64t t1 = MUL2(sp, p1);
        u64t zc = MUL2(zp, cop);
        u64t tp = FMA2(zc, p2, t1);
        u64t y1p = MUL2(ap, tp);
        u64t ep = MUL2(epsn, ip);                  // -eps*invr
        u64t ie = FMA2(ep, ip, ip);                // ~ 1/(r+eps)
        u64t wp = MUL2(hp, ie);
        acc = FMA2(y1p, wp, acc);
    }
    return acc;
}

// SMALL branch (x < 8): NR rational + 0.6366*(J1*log x - 1/x)
__device__ __forceinline__ u64t seg_small(const float* __restrict__ gc,
                                          const float* __restrict__ gh,
                                          int lo, int hi, int lane,
                                          float u, float d2, u64t acc) {
    u64t nup = F2c(-u), d2p = F2c(d2);
    u64t k15 = F2c(15.0f);
    u64t J5 = F2c(-30.16036606f), J4 = F2c(15704.48260f), J3 = F2c(-2972611.439f);
    u64t J2 = F2c(242396853.1f), J1c = F2c(-7895059235.0f), J0 = F2c(72362614232.0f);
    u64t JD4 = F2c(376.9991397f), JD3 = F2c(99447.43394f), JD2 = F2c(18583304.74f);
    u64t JD1 = F2c(2300535178.0f), JD0 = F2c(144725228442.0f);
    u64t Y5 = F2c(8.511937935e4f), Y4 = F2c(-4.237922726e7f), Y3 = F2c(7.349264551e9f);
    u64t Y2 = F2c(-5.153438139e11f), Y1C = F2c(1.275274390e13f), Y0 = F2c(-4.900604943e13f);
    u64t YD5 = F2c(3.549632885e3f), YD4 = F2c(1.020426050e6f), YD3 = F2c(2.245904002e8f);
    u64t YD2 = F2c(3.733650367e10f), YD1 = F2c(4.244419664e12f), YD0 = F2c(2.499580570e14f);
    u64t m115 = F2c(-1.0f / 15.0f);
    u64t c636 = F2c(0.636619772f);
    u64t epsn = F2c(-1e-8f);

    #pragma unroll 2
    for (int j = lo + 2 * lane; j < hi; j += 64) {
        u64t cp = *(const u64t*)(gc + j);
        u64t hp = *(const u64t*)(gh + j);
        u64t dup = ADD2(cp, nup);
        u64t r2p = FMA2(dup, dup, d2p);
        float r20, r21; UPK(r2p, r20, r21);
        r20 = fmaxf(r20, 1e-24f); r21 = fmaxf(r21, 1e-24f);
        float i0 = rsqrtf(r20), i1 = rsqrtf(r21);
        u64t ip = F2(i0, i1);
        u64t r2g = F2(r20, r21);
        u64t rp = MUL2(r2g, ip);
        u64t xp = MUL2(k15, rp);                     // x = 15r
        u64t yp = MUL2(xp, xp);
        // J1 num/den
        u64t jn = FMA2(yp, J5, J4);
        jn = FMA2(yp, jn, J3); jn = FMA2(yp, jn, J2);
        jn = FMA2(yp, jn, J1c); jn = FMA2(yp, jn, J0);
        jn = MUL2(jn, xp);
        u64t jd = ADD2(yp, JD4);
        jd = FMA2(yp, jd, JD3); jd = FMA2(yp, jd, JD2);
        jd = FMA2(yp, jd, JD1); jd = FMA2(yp, jd, JD0);
        // Y1 num/den
        u64t yn = FMA2(yp, Y5, Y4);
        yn = FMA2(yp, yn, Y3); yn = FMA2(yp, yn, Y2);
        yn = FMA2(yp, yn, Y1C); yn = FMA2(yp, yn, Y0);
        yn = MUL2(yn, xp);
        u64t yd = ADD2(yp, YD5);
        yd = FMA2(yp, yd, YD4); yd = FMA2(yp, yd, YD3);
        yd = FMA2(yp, yd, YD2); yd = FMA2(yp, yd, YD1); yd = FMA2(yp, yd, YD0);
        // one rcp serves both rationals
        u64t prod = MUL2(jd, yd);
        float pr0, pr1; UPK(prod, pr0, pr1);
        u64t rden = F2(rcpf(pr0), rcpf(pr1));
        u64t j1v = MUL2(MUL2(jn, yd), rden);
        u64t ysv = MUL2(MUL2(yn, jd), rden);
        float x0, x1; UPK(xp, x0, x1);
        u64t lgp = F2(__logf(x0), __logf(x1));
        u64t invxn = MUL2(ip, m115);                 // -1/x
        u64t inner = FMA2(j1v, lgp, invxn);          // J1*log(x) - 1/x
        u64t y1p = FMA2(c636, inner, ysv);
        u64t ep = MUL2(epsn, ip);
        u64t ie = FMA2(ep, ip, ip);                  // ~ 1/(r+eps)
        u64t wp = MUL2(hp, ie);
        acc = FMA2(y1p, wp, acc);
    }
    return acc;
}

// ============================== main kernel =================================
// One warp per query; per side the small-branch j's are a contiguous interval
// computed analytically (warp-uniform) -> three branch-free packed segments.
__global__ void __launch_bounds__(128) bem_main_packed(
        const float* __restrict__ points,
        const float* __restrict__ dyp,
        float* __restrict__ out, int P, int Nside) {
    int gwarp = (blockIdx.x * blockDim.x + threadIdx.x) >> 5;
    int lane = threadIdx.x & 31;
    if (gwarp >= P) return;
    float px = points[2 * gwarp];
    float py = points[2 * gwarp + 1];

    float a = g_cord[0];
    float last = g_cord[Nside - 1];
    float invstep = (float)(Nside - 1) * rcpf(last - a);

    float part = 0.0f;
    #pragma unroll
    for (int s = 0; s < 4; ++s) {
        float c = (s == 0) ? (py - 1.0f) : (s == 1) ? (-py)
                : (s == 2) ? (-px) : (px - 1.0f);
        float u = (s < 2) ? px : py;
        float d2 = c * c;
        const float* gc = g_cord + s * Nside;
        const float* gh = g_h + s * Nside;

        // analytic small-branch interval: (u-cord)^2 < (8/15)^2 - c^2
        int jlo = 0, jhi = 0;
        float t2 = 0.2844444444f - d2;
        if (t2 > 0.0f) {
            float t = sqrtf(t2);
            jlo = (int)ceilf((u - t - a) * invstep);
            jhi = (int)floorf((u + t - a) * invstep) + 1;
            jlo = max(jlo, 0); jlo = min(jlo, Nside);
            jhi = max(jhi, 0); jhi = min(jhi, Nside);
            jlo &= ~1;                       // even-align (branch-robust at x~8)
            jhi = (jhi + 1) & ~1;
            if (jhi > Nside) jhi = Nside;
            if (jhi < jlo) jhi = jlo;
        }

        u64t acc2 = 0ULL;                    // (0.f, 0.f)
        acc2 = seg_large(gc, gh, 0,   jlo,   lane, u, d2, acc2);
        acc2 = seg_large(gc, gh, jhi, Nside, lane, u, d2, acc2);
        acc2 = seg_small(gc, gh, jlo, jhi,   lane, u, d2, acc2);
        float aL, aH; UPK(acc2, aL, aH);
        part = fmaf(c, aL + aH, part);
    }
    #pragma unroll
    for (int o = 16; o > 0; o >>= 1)
        part += __shfl_down_sync(0xffffffffu, part, o);
    if (lane == 0)
        out[gwarp] = 0.25f * 15.0f * dyp[0] * part;
}

// ================= scalar fallback main (odd Nside safety) ==================
__device__ __forceinline__ float y1_eval(float x, float invr) {
    if (x < 8.0f) {
        float y = x * x;
        float jn = fmaf(y, -30.16036606f, 15704.48260f);
        jn = fmaf(y, jn, -2972611.439f); jn = fmaf(y, jn, 242396853.1f);
        jn = fmaf(y, jn, -7895059235.0f); jn = fmaf(y, jn, 72362614232.0f);
        jn *= x;
        float jd = y + 376.9991397f;
        jd = fmaf(y, jd, 99447.43394f); jd = fmaf(y, jd, 18583304.74f);
        jd = fmaf(y, jd, 2300535178.0f); jd = fmaf(y, jd, 144725228442.0f);
        float yn = fmaf(y, 8.511937935e4f, -4.237922726e7f);
        yn = fmaf(y, yn, 7.349264551e9f); yn = fmaf(y, yn, -5.153438139e11f);
        yn = fmaf(y, yn, 1.275274390e13f); yn = fmaf(y, yn, -4.900604943e13f);
        yn *= x;
        float yd = y + 3.549632885e3f;
        yd = fmaf(y, yd, 1.020426050e6f); yd = fmaf(y, yd, 2.245904002e8f);
        yd = fmaf(y, yd, 3.733650367e10f); yd = fmaf(y, yd, 4.244419664e12f);
        yd = fmaf(y, yd, 2.499580570e14f);
        float rden = rcpf(jd * yd);
        float j1 = jn * yd * rden;
        float ys = yn * jd * rden;
        float lg = __logf(x);
        float invx = invr * (1.0f / 15.0f);
        return fmaf(0.636619772f, fmaf(j1, lg, -invx), ys);
    } else {
        float z = (8.0f / 15.0f) * invr;
        float y2 = z * z;
        float xx = x - 2.356194491f;
        float p1 = fmaf(y2, -0.240337019e-6f, 0.2457520174e-5f);
        p1 = fmaf(y2, p1, -0.3516396496e-4f); p1 = fmaf(y2, p1, 0.183105e-2f);
        p1 = fmaf(y2, p1, 1.0f);
        float p2 = fmaf(y2, 0.105787412e-6f, -0.88228987e-6f);
        p2 = fmaf(y2, p2, 0.8449199096e-5f); p2 = fmaf(y2, p2, -0.2002690873e-3f);
        p2 = fmaf(y2, p2, 0.04687499995f);
        float amp = rsqrtf(x * 1.5707963268f);
        float s, cc;
        __sincosf(xx, &s, &cc);
        return amp * fmaf(z, cc * p2, s * p1);
    }
}
__global__ void __launch_bounds__(128) bem_main_scalar(
        const float* __restrict__ points, const float* __restrict__ dyp,
        float* __restrict__ out, int P, int Nside) {
    int gwarp = (blockIdx.x * blockDim.x + threadIdx.x) >> 5;
    int lane = threadIdx.x & 31;
    if (gwarp >= P) return;
    float px = points[2 * gwarp], py = points[2 * gwarp + 1];
    float part = 0.0f;
    #pragma unroll
    for (int s = 0; s < 4; ++s) {
        float c = (s == 0) ? (py - 1.0f) : (s == 1) ? (-py)
                : (s == 2) ? (-px) : (px - 1.0f);
        float u = (s < 2) ? px : py;
        float d2 = c * c;
        const float* gc = g_cord + s * Nside;
        const float* gh = g_h + s * Nside;
        float acc = 0.0f;
        for (int j = lane; j < Nside; j += 32) {
            float du = u - gc[j];
            float r2 = fmaxf(fmaf(du, du, d2), 1e-24f);
            float invr = rsqrtf(r2);
            float r = r2 * invr;
            float invre = invr - 1e-8f * invr * invr;
            acc = fmaf(y1_eval(15.0f * r, invr), gh[j] * invre, acc);
        }
        part = fmaf(c, acc, part);
    }
    #pragma unroll
    for (int o = 16; o > 0; o >>= 1)
        part += __shfl_down_sync(0xffffffffu, part, o);
    if (lane == 0) out[gwarp] = 0.25f * 15.0f * dyp[0] * part;
}

// ================================ launch ====================================
extern "C" void kernel_launch(void* const* d_in, const int* in_sizes, int n_in,
                              void* d_out, int out_size) {
    const float* points = (const float*)d_in[0];
    const float* bp     = (const float*)d_in[1];
    const float* dy     = (const float*)d_in[3];
    const float* W1 = (const float*)d_in[4];
    const float* b1 = (const float*)d_in[5];
    const float* W2 = (const float*)d_in[6];
    const float* b2 = (const float*)d_in[7];
    const float* W3 = (const float*)d_in[8];
    const float* b3 = (const float*)d_in[9];
    const float* W4 = (const float*)d_in[10];
    const float* b4 = (const float*)d_in[11];
    const float* W5 = (const float*)d_in[12];
    const float* b5 = (const float*)d_in[13];

    int P = in_sizes[0] / 2;
    int M = in_sizes[1] / 2;
    int H = in_sizes[5];
    int Nside = M / 4;

    if (H == HID && (M % PTS_PER_BLK) == 0) {
        mlp_fused_kernel<<<M / PTS_PER_BLK, 256>>>(bp, W1, b1, W2, b2, W3, b3,
                                                   W4, b4, W5, b5, Nside);
    } else {
        int nh = M * H, tb = 256, gh = (nh + tb - 1) / tb;
        mlp_l1_kernel<<<gh, tb>>>(bp, W1, b1, M, H);
        mlp_mid_kernel<<<gh, tb>>>(W2, b2, M, H, 0);
        mlp_mid_kernel<<<gh, tb>>>(W3, b3, M, H, 1);
        mlp_mid_kernel<<<gh, tb>>>(W4, b4, M, H, 0);
        mlp_out_kernel<<<(M + tb - 1) / tb, tb>>>(W5, b5, bp, M, H, Nside, 1);
    }

    long long total = (long long)P * 32;
    int mb = 128;
    int mg = (int)((total + mb - 1) / mb);
    if ((Nside & 1) == 0 && Nside >= 2) {
        bem_main_packed<<<mg, mb>>>(points, dy, (float*)d_out, P, Nside);
    } else {
        bem_main_scalar<<<mg, mb>>>(points, dy, (float*)d_out, P, Nside);
    }
}

// round 3
// speedup vs baseline: 2.2491x; 1.8408x over previous
#include <cuda_runtime.h>

// ---------------------------------------------------------------------------
// u[i] = 0.25*k*dy * sum_j Y1(k*r_ij) * (diff.n_j)/(r_ij+eps) * h_j
// Sides of unit square: diff.n = c_s const per query; r^2=(u-cord_j)^2+c_s^2.
// Core trick: G(r) = Y1(15 r)/(r+eps) is 1-D  ->  shared-mem LUT + lerp.
// Near-field (r < RNEAR, where G is singular) is an analytic contiguous
// j-interval per (query,side) -> exact NR evaluation there only.
// ---------------------------------------------------------------------------

#define MAXM 4096
#define MAXH 64

#define HID 50
#define PTS_PER_BLK 32

#define TABN   1536
#define R0f    0.078125f          // table start (80 * 2^-10)
#define DRf    0.0009765625f      // 2^-10 step
#define SCALEf 1024.0f
#define OFFSf  (-80.0f)           // -R0*SCALE
#define RNEARf 0.0801f            // exact-eval threshold (> R0 + pad slop)

// scratch (no allocations allowed)
__device__ float  g_buf1[MAXM * MAXH];
__device__ float  g_buf2[MAXM * MAXH];
__device__ __align__(16) float g_cord[MAXM];
__device__ __align__(16) float g_h[MAXM];
__device__ __align__(16) float2 g_tab[TABN + 8];

__device__ __forceinline__ float sqrt_apx(float x) {
    float r; asm("sqrt.approx.f32 %0,%1;" : "=f"(r) : "f"(x)); return r;
}
__device__ __forceinline__ float rcpf(float x) {
    float r; asm("rcp.approx.f32 %0,%1;" : "=f"(r) : "f"(x)); return r;
}

// ===================== accurate Y1 (builder + near-field) ===================
__device__ float bessel_j1_ref(float x) {
    float ax = fabsf(x);
    if (ax < 8.0f) {
        float y = x * x;
        float num = x * (72362614232.0f + y * (-7895059235.0f + y * (242396853.1f +
                    y * (-2972611.439f + y * (15704.48260f + y * (-30.16036606f))))));
        float den = 144725228442.0f + y * (2300535178.0f + y * (18583304.74f +
                    y * (99447.43394f + y * (376.9991397f + y))));
        return num / den;
    } else {
        float z = 8.0f / ax;
        float y2 = z * z;
        float xx = ax - 2.356194491f;
        float p1 = 1.0f + y2 * (0.183105e-2f + y2 * (-0.3516396496e-4f +
                   y2 * (0.2457520174e-5f + y2 * (-0.240337019e-6f))));
        float p2 = 0.04687499995f + y2 * (-0.2002690873e-3f + y2 * (0.8449199096e-5f +
                   y2 * (-0.88228987e-6f + y2 * 0.105787412e-6f)));
        float v = sqrtf(0.636619772f / ax) * (cosf(xx) * p1 - z * sinf(xx) * p2);
        return (x < 0.0f) ? -v : v;
    }
}
__device__ float bessel_y1_ref(float x) {
    float xs = fmaxf(x, 1e-12f);
    if (xs < 8.0f) {
        float y = xs * xs;
        float num = xs * (-4.900604943e13f + y * (1.275274390e13f + y * (-5.153438139e11f +
                    y * (7.349264551e9f + y * (-4.237922726e7f + y * 8.511937935e4f)))));
        float den = 2.499580570e14f + y * (4.244419664e12f + y * (3.733650367e10f +
                    y * (2.245904002e8f + y * (1.020426050e6f + y * (3.549632885e3f + y)))));
        return num / den + 0.636619772f * (bessel_j1_ref(xs) * logf(xs) - 1.0f / xs);
    } else {
        float z = 8.0f / xs;
        float y2 = z * z;
        float xx = xs - 2.356194491f;
        float p1 = 1.0f + y2 * (0.183105e-2f + y2 * (-0.3516396496e-4f +
                   y2 * (0.2457520174e-5f + y2 * (-0.240337019e-6f))));
        float p2 = 0.04687499995f + y2 * (-0.2002690873e-3f + y2 * (0.8449199096e-5f +
                   y2 * (-0.88228987e-6f + y2 * 0.105787412e-6f)));
        return sqrtf(0.636619772f / xs) * (sinf(xx) * p1 + z * cosf(xx) * p2);
    }
}

// table builder: G(r) = Y1(15 r)/(r + 1e-8), value + forward slope
__global__ void build_tab_kernel() {
    int i = blockIdx.x * blockDim.x + threadIdx.x;
    if (i >= TABN + 8) return;
    float r0 = fmaf((float)i, DRf, R0f);
    float r1 = r0 + DRf;
    float v0 = bessel_y1_ref(15.0f * r0) / (r0 + 1e-8f);
    float v1 = bessel_y1_ref(15.0f * r1) / (r1 + 1e-8f);
    g_tab[i] = make_float2(v0, v1 - v0);
}

// ========================= fused MLP (H == 50) ==============================
__global__ void __launch_bounds__(256) mlp_fused_kernel(
        const float* __restrict__ bp,
        const float* __restrict__ W1, const float* __restrict__ b1,
        const float* __restrict__ W2, const float* __restrict__ b2,
        const float* __restrict__ W3, const float* __restrict__ b3,
        const float* __restrict__ W4, const float* __restrict__ b4,
        const float* __restrict__ W5, const float* __restrict__ b5,
        int Nside) {
    __shared__ float sW2[HID * HID], sW3[HID * HID], sW4[HID * HID];
    __shared__ float sW1[2 * HID], sW5[HID];
    __shared__ float sb1[HID], sb2[HID], sb3[HID], sb4[HID];
    __shared__ float sA[PTS_PER_BLK][HID], sB[PTS_PER_BLK][HID];

    int tid = threadIdx.x;
    for (int i = tid; i < HID * HID; i += 256) {
        sW2[i] = W2[i]; sW3[i] = W3[i]; sW4[i] = W4[i];
    }
    if (tid < 2 * HID) sW1[tid] = W1[tid];
    if (tid < HID) {
        sW5[tid] = W5[tid];
        sb1[tid] = b1[tid]; sb2[tid] = b2[tid];
        sb3[tid] = b3[tid]; sb4[tid] = b4[tid];
    }
    int p0 = blockIdx.x * PTS_PER_BLK;
    __syncthreads();

    for (int t = tid; t < PTS_PER_BLK * HID; t += 256) {
        int i = t / HID, j = t - i * HID;
        int gi = p0 + i;
        float x0 = bp[2 * gi], x1 = bp[2 * gi + 1];
        sA[i][j] = tanhf(fmaf(x0, sW1[j], fmaf(x1, sW1[HID + j], sb1[j])));
    }
    __syncthreads();
    for (int t = tid; t < PTS_PER_BLK * HID; t += 256) {
        int i = t / HID, j = t - i * HID;
        float acc = sb2[j];
        #pragma unroll
        for (int k = 0; k < HID; ++k) acc = fmaf(sA[i][k], sW2[k * HID + j], acc);
        sB[i][j] = tanhf(acc);
    }
    __syncthreads();
    for (int t = tid; t < PTS_PER_BLK * HID; t += 256) {
        int i = t / HID, j = t - i * HID;
        float acc = sb3[j];
        #pragma unroll
        for (int k = 0; k < HID; ++k) acc = fmaf(sB[i][k], sW3[k * HID + j], acc);
        sA[i][j] = tanhf(acc);
    }
    __syncthreads();
    for (int t = tid; t < PTS_PER_BLK * HID; t += 256) {
        int i = t / HID, j = t - i * HID;
        float acc = sb4[j];
        #pragma unroll
        for (int k = 0; k < HID; ++k) acc = fmaf(sA[i][k], sW4[k * HID + j], acc);
        sB[i][j] = tanhf(acc);
    }
    __syncthreads();
    for (int i = tid; i < PTS_PER_BLK; i += 256) {
        int gi = p0 + i;
        float acc = b5[0];
        #pragma unroll
        for (int k = 0; k < HID; ++k) acc = fmaf(sB[i][k], sW5[k], acc);
        int side = gi / Nside;
        float u = (side < 2) ? bp[2 * gi] : bp[2 * gi + 1];
        g_cord[gi] = u;
        g_h[gi] = acc;
    }
}

// ===================== fallback layered MLP (H != 50) =======================
__global__ void mlp_l1_kernel(const float* __restrict__ bp,
                              const float* __restrict__ W1,
                              const float* __restrict__ b1, int M, int H) {
    int idx = blockIdx.x * blockDim.x + threadIdx.x;
    if (idx >= M * H) return;
    int i = idx / H, j = idx - i * H;
    float v = fmaf(bp[2 * i + 1], W1[H + j], b1[j]);
    v = fmaf(bp[2 * i], W1[j], v);
    g_buf1[idx] = tanhf(v);
}
__global__ void mlp_mid_kernel(const float* __restrict__ W,
                               const float* __restrict__ b, int M, int H, int dir) {
    int idx = blockIdx.x * blockDim.x + threadIdx.x;
    if (idx >= M * H) return;
    int i = idx / H, j = idx - i * H;
    const float* in  = dir ? g_buf2 : g_buf1;
    float*       out = dir ? g_buf1 : g_buf2;
    float acc = b[j];
    const float* row = in + i * H;
    for (int k = 0; k < H; ++k) acc = fmaf(row[k], W[k * H + j], acc);
    out[idx] = tanhf(acc);
}
__global__ void mlp_out_kernel(const float* __restrict__ W5,
                               const float* __restrict__ b5,
                               const float* __restrict__ bp,
                               int M, int H, int Nside, int src) {
    int i = blockIdx.x * blockDim.x + threadIdx.x;
    if (i >= M) return;
    const float* in = src ? g_buf2 : g_buf1;
    float acc = b5[0];
    const float* row = in + i * H;
    for (int k = 0; k < H; ++k) acc = fmaf(row[k], W5[k], acc);
    int side = i / Nside;
    float u = (side < 2) ? bp[2 * i] : bp[2 * i + 1];
    g_cord[i] = u;
    g_h[i] = acc;
}

// ====================== exact near-field Y1 (x < 8) =========================
__device__ __forceinline__ float y1_small(float x, float invr) {
    float y = x * x;
    float jn = fmaf(y, -30.16036606f, 15704.48260f);
    jn = fmaf(y, jn, -2972611.439f); jn = fmaf(y, jn, 242396853.1f);
    jn = fmaf(y, jn, -7895059235.0f); jn = fmaf(y, jn, 72362614232.0f);
    jn *= x;
    float jd = y + 376.9991397f;
    jd = fmaf(y, jd, 99447.43394f); jd = fmaf(y, jd, 18583304.74f);
    jd = fmaf(y, jd, 2300535178.0f); jd = fmaf(y, jd, 144725228442.0f);
    float yn = fmaf(y, 8.511937935e4f, -4.237922726e7f);
    yn = fmaf(y, yn, 7.349264551e9f); yn = fmaf(y, yn, -5.153438139e11f);
    yn = fmaf(y, yn, 1.275274390e13f); yn = fmaf(y, yn, -4.900604943e13f);
    yn *= x;
    float yd = y + 3.549632885e3f;
    yd = fmaf(y, yd, 1.020426050e6f); yd = fmaf(y, yd, 2.245904002e8f);
    yd = fmaf(y, yd, 3.733650367e10f); yd = fmaf(y, yd, 4.244419664e12f);
    yd = fmaf(y, yd, 2.499580570e14f);
    float rden = rcpf(jd * yd);
    float j1 = jn * yd * rden;
    float ys = yn * jd * rden;
    float lg = __logf(x);
    float invx = invr * (1.0f / 15.0f);
    return fmaf(0.636619772f, fmaf(j1, lg, -invx), ys);
}

// ============================ LUT main kernel ===============================
__global__ void __launch_bounds__(256) bem_lut_kernel(
        const float* __restrict__ points,
        const float* __restrict__ dyp,
        float* __restrict__ out, int P, int Nside) {
    __shared__ __align__(16) float2 stab[TABN];
    for (int i = threadIdx.x; i < TABN; i += 256) stab[i] = g_tab[i];
    __syncthreads();

    int warp = (blockIdx.x * blockDim.x + threadIdx.x) >> 5;
    int lane = threadIdx.x & 31;
    if (warp >= P) return;

    float px = points[2 * warp];
    float py = points[2 * warp + 1];

    float a = g_cord[0];
    float step = (g_cord[Nside - 1] - a) / (float)(Nside - 1);
    float invstep = 1.0f / step;
    float step64 = step * 64.0f;

    float part = 0.0f;
    #pragma unroll
    for (int s = 0; s < 4; ++s) {
        float c = (s == 0) ? (py - 1.0f) : (s == 1) ? (-py)
                : (s == 2) ? (-px) : (px - 1.0f);
        float u = (s < 2) ? px : py;
        float d2 = c * c;
        int off = s * Nside;

        // analytic near-field interval: (u-cord)^2 < RNEAR^2 - c^2
        int jlo = 0, jhi = 0;
        float t2 = RNEARf * RNEARf - d2;
        if (t2 > 0.0f) {
            float hw = sqrtf(t2);
            jlo = (int)floorf((u - hw - a) * invstep);        // pad down
            jhi = (int)ceilf((u + hw - a) * invstep) + 1;     // pad up
            jlo = max(jlo, 0); jlo = min(jlo, Nside);
            jhi = max(jhi, 0); jhi = min(jhi, Nside);
            jlo &= ~1;
            jhi = (jhi + 1) & ~1;
            if (jhi > Nside) jhi = Nside;
            if (jhi < jlo) jhi = jlo;
        }

        float accA = 0.0f, accB = 0.0f;

        // --- LUT sweep over [lo,hi), 2 pairs per lane-iter ---
        #pragma unroll 1
        for (int rg = 0; rg < 2; ++rg) {
            int lo = rg ? jhi : 0;
            int hi = rg ? Nside : jlo;
            int j0 = lo + 2 * lane;
            float du = u - fmaf((float)j0, step, a);
            #pragma unroll 2
            for (int j = j0; j < hi; j += 64) {
                float2 hv = *(const float2*)(g_h + off + j);
                float du2 = du - step;
                float r2a = fmaf(du, du, d2);
                float r2b = fmaf(du2, du2, d2);
                float ra = sqrt_apx(r2a);
                float rb = sqrt_apx(r2b);
                float ta = fmaxf(fmaf(ra, SCALEf, OFFSf), 0.0f);
                float tb = fmaxf(fmaf(rb, SCALEf, OFFSf), 0.0f);
                int ia = min((int)ta, TABN - 2);
                int ib = min((int)tb, TABN - 2);
                float fa = ta - (float)ia;
                float fb = tb - (float)ib;
                float2 ea = stab[ia];
                float2 eb = stab[ib];
                accA = fmaf(fmaf(fa, ea.y, ea.x), hv.x, accA);
                accB = fmaf(fmaf(fb, eb.y, eb.x), hv.y, accB);
                du -= step64;
            }
        }

        // --- exact near-field interval (x = 15 r < 1.3 << 8 always) ---
        float accN = 0.0f;
        for (int j = jlo + lane; j < jhi; j += 32) {
            float cord = g_cord[off + j];
            float hval = g_h[off + j];
            float du = u - cord;
            float r2 = fmaxf(fmaf(du, du, d2), 1e-24f);
            float invr = rsqrtf(r2);
            float r = r2 * invr;
            float invre = invr - 1e-8f * invr * invr;   // ~1/(r+eps)
            float y1 = y1_small(15.0f * r, invr);
            accN = fmaf(y1, hval * invre, accN);
        }

        part = fmaf(c, (accA + accB) + accN, part);
    }

    #pragma unroll
    for (int o = 16; o > 0; o >>= 1)
        part += __shfl_down_sync(0xffffffffu, part, o);
    if (lane == 0)
        out[warp] = 0.25f * 15.0f * dyp[0] * part;
}

// ================= scalar fallback main (odd/small Nside) ===================
__device__ __forceinline__ float y1_eval_full(float x, float invr) {
    if (x < 8.0f) {
        return y1_small(x, invr);
    } else {
        float z = (8.0f / 15.0f) * invr;
        float y2 = z * z;
        float xx = x - 2.356194491f;
        float p1 = fmaf(y2, -0.240337019e-6f, 0.2457520174e-5f);
        p1 = fmaf(y2, p1, -0.3516396496e-4f); p1 = fmaf(y2, p1, 0.183105e-2f);
        p1 = fmaf(y2, p1, 1.0f);
        float p2 = fmaf(y2, 0.105787412e-6f, -0.88228987e-6f);
        p2 = fmaf(y2, p2, 0.8449199096e-5f); p2 = fmaf(y2, p2, -0.2002690873e-3f);
        p2 = fmaf(y2, p2, 0.04687499995f);
        float amp = rsqrtf(x * 1.5707963268f);
        float sn, cc;
        __sincosf(xx, &sn, &cc);
        return amp * fmaf(z, cc * p2, sn * p1);
    }
}
__global__ void __launch_bounds__(128) bem_main_scalar(
        const float* __restrict__ points, const float* __restrict__ dyp,
        float* __restrict__ out, int P, int Nside) {
    int gwarp = (blockIdx.x * blockDim.x + threadIdx.x) >> 5;
    int lane = threadIdx.x & 31;
    if (gwarp >= P) return;
    float px = points[2 * gwarp], py = points[2 * gwarp + 1];
    float part = 0.0f;
    #pragma unroll
    for (int s = 0; s < 4; ++s) {
        float c = (s == 0) ? (py - 1.0f) : (s == 1) ? (-py)
                : (s == 2) ? (-px) : (px - 1.0f);
        float u = (s < 2) ? px : py;
        float d2 = c * c;
        const float* gc = g_cord + s * Nside;
        const float* gh = g_h + s * Nside;
        float acc = 0.0f;
        for (int j = lane; j < Nside; j += 32) {
            float du = u - gc[j];
            float r2 = fmaxf(fmaf(du, du, d2), 1e-24f);
            float invr = rsqrtf(r2);
            float r = r2 * invr;
            float invre = invr - 1e-8f * invr * invr;
            acc = fmaf(y1_eval_full(15.0f * r, invr), gh[j] * invre, acc);
        }
        part = fmaf(c, acc, part);
    }
    #pragma unroll
    for (int o = 16; o > 0; o >>= 1)
        part += __shfl_down_sync(0xffffffffu, part, o);
    if (lane == 0) out[gwarp] = 0.25f * 15.0f * dyp[0] * part;
}

// ================================ launch ====================================
extern "C" void kernel_launch(void* const* d_in, const int* in_sizes, int n_in,
                              void* d_out, int out_size) {
    const float* points = (const float*)d_in[0];
    const float* bp     = (const float*)d_in[1];
    const float* dy     = (const float*)d_in[3];
    const float* W1 = (const float*)d_in[4];
    const float* b1 = (const float*)d_in[5];
    const float* W2 = (const float*)d_in[6];
    const float* b2 = (const float*)d_in[7];
    const float* W3 = (const float*)d_in[8];
    const float* b3 = (const float*)d_in[9];
    const float* W4 = (const float*)d_in[10];
    const float* b4 = (const float*)d_in[11];
    const float* W5 = (const float*)d_in[12];
    const float* b5 = (const float*)d_in[13];

    int P = in_sizes[0] / 2;
    int M = in_sizes[1] / 2;
    int H = in_sizes[5];
    int Nside = M / 4;

    build_tab_kernel<<<(TABN + 8 + 127) / 128, 128>>>();

    if (H == HID && (M % PTS_PER_BLK) == 0) {
        mlp_fused_kernel<<<M / PTS_PER_BLK, 256>>>(bp, W1, b1, W2, b2, W3, b3,
                                                   W4, b4, W5, b5, Nside);
    } else {
        int nh = M * H, tb = 256, gh = (nh + tb - 1) / tb;
        mlp_l1_kernel<<<gh, tb>>>(bp, W1, b1, M, H);
        mlp_mid_kernel<<<gh, tb>>>(W2, b2, M, H, 0);
        mlp_mid_kernel<<<gh, tb>>>(W3, b3, M, H, 1);
        mlp_mid_kernel<<<gh, tb>>>(W4, b4, M, H, 0);
        mlp_out_kernel<<<(M + tb - 1) / tb, tb>>>(W5, b5, bp, M, H, Nside, 1);
    }

    long long total = (long long)P * 32;
    if ((Nside & 1) == 0 && Nside >= 64) {
        int mb = 256;
        int mg = (int)((total + mb - 1) / mb);
        bem_lut_kernel<<<mg, mb>>>(points, dy, (float*)d_out, P, Nside);
    } else {
        int mb = 128;
        int mg = (int)((total + mb - 1) / mb);
        bem_main_scalar<<<mg, mb>>>(points, dy, (float*)d_out, P, Nside);
    }
}

// round 6
// speedup vs baseline: 2.4564x; 1.0922x over previous
#include <cuda_runtime.h>

// ---------------------------------------------------------------------------
// u[i] = 0.25*k*dy * sum_j Y1(k*r_ij) * (diff.n_j)/(r_ij+eps) * h_j
// Per side of unit square: diff.n = c_s (const per query), r^2=(u-cord)^2+c^2.
// G(r) = Y1(15r)/(r+eps) -> shared-mem LUT + midpoint lerp, FULL branch-free
// sweep; near-field (r<RNEAR) adds (exact - lut) correction on an analytic
// contiguous j-interval. Magic-constant rounding, interleaved lane mapping.
// ---------------------------------------------------------------------------

#define MAXM 4096
#define MAXH 64

#define HID 50
#define PTS_PER_BLK 32

#define TABN    1536
#define R0f     0.078125f         // table start
#define SCALEf  1024.0f
#define OFFSf   (-80.0f)          // -R0*SCALE
#define DRf     0.0009765625f     // 1/SCALE
#define RNEARf  0.0801f           // exact-correction threshold (> R0)
#define MAGICf  12582912.0f       // 1.5 * 2^23

#define TAB_BLOCKS 8

// scratch (no allocations allowed)
__device__ float  g_buf1[MAXM * MAXH];
__device__ float  g_buf2[MAXM * MAXH];
__device__ __align__(16) float g_cord[MAXM];
__device__ __align__(16) float g_h[MAXM];
__device__ __align__(16) float2 g_tab[TABN + 8];

__device__ __forceinline__ float sqrt_apx(float x) {
    float r; asm("sqrt.approx.f32 %0,%1;" : "=f"(r) : "f"(x)); return r;
}
__device__ __forceinline__ float rcpf(float x) {
    float r; asm("rcp.approx.f32 %0,%1;" : "=f"(r) : "f"(x)); return r;
}

// ============== Y1 reference (table builder; fast intrinsics) ===============
__device__ float bessel_j1_fast(float x) {
    float ax = fabsf(x);
    if (ax < 8.0f) {
        float y = x * x;
        float num = x * (72362614232.0f + y * (-7895059235.0f + y * (242396853.1f +
                    y * (-2972611.439f + y * (15704.48260f + y * (-30.16036606f))))));
        float den = 144725228442.0f + y * (2300535178.0f + y * (18583304.74f +
                    y * (99447.43394f + y * (376.9991397f + y))));
        return num / den;
    } else {
        float z = 8.0f / ax;
        float y2 = z * z;
        float xx = ax - 2.356194491f;
        float p1 = 1.0f + y2 * (0.183105e-2f + y2 * (-0.3516396496e-4f +
                   y2 * (0.2457520174e-5f + y2 * (-0.240337019e-6f))));
        float p2 = 0.04687499995f + y2 * (-0.2002690873e-3f + y2 * (0.8449199096e-5f +
                   y2 * (-0.88228987e-6f + y2 * 0.105787412e-6f)));
        float v = sqrtf(0.636619772f / ax) * (__cosf(xx) * p1 - z * __sinf(xx) * p2);
        return (x < 0.0f) ? -v : v;
    }
}
__device__ float bessel_y1_fast(float x) {
    float xs = fmaxf(x, 1e-12f);
    if (xs < 8.0f) {
        float y = xs * xs;
        float num = xs * (-4.900604943e13f + y * (1.275274390e13f + y * (-5.153438139e11f +
                    y * (7.349264551e9f + y * (-4.237922726e7f + y * 8.511937935e4f)))));
        float den = 2.499580570e14f + y * (4.244419664e12f + y * (3.733650367e10f +
                    y * (2.245904002e8f + y * (1.020426050e6f + y * (3.549632885e3f + y)))));
        return num / den + 0.636619772f * (bessel_j1_fast(xs) * __logf(xs) - 1.0f / xs);
    } else {
        float z = 8.0f / xs;
        float y2 = z * z;
        float xx = xs - 2.356194491f;
        float p1 = 1.0f + y2 * (0.183105e-2f + y2 * (-0.3516396496e-4f +
                   y2 * (0.2457520174e-5f + y2 * (-0.240337019e-6f))));
        float p2 = 0.04687499995f + y2 * (-0.2002690873e-3f + y2 * (0.8449199096e-5f +
                   y2 * (-0.88228987e-6f + y2 * 0.105787412e-6f)));
        return sqrtf(0.636619772f / xs) * (__sinf(xx) * p1 + z * __cosf(xx) * p2);
    }
}

// =============== fused prep kernel: MLP blocks + table blocks ===============
__global__ void __launch_bounds__(256) prep_kernel(
        const float* __restrict__ bp,
        const float* __restrict__ W1, const float* __restrict__ b1,
        const float* __restrict__ W2, const float* __restrict__ b2,
        const float* __restrict__ W3, const float* __restrict__ b3,
        const float* __restrict__ W4, const float* __restrict__ b4,
        const float* __restrict__ W5, const float* __restrict__ b5,
        int Nside, int mlp_blocks) {
    if (blockIdx.x >= (unsigned)mlp_blocks) {
        // ---- table builder blocks ----
        int i = (blockIdx.x - mlp_blocks) * 256 + threadIdx.x;
        if (i < TABN + 8) {
            float r0 = fmaf((float)i, DRf, R0f);
            float r1 = r0 + DRf;
            float v0 = bessel_y1_fast(15.0f * r0) / (r0 + 1e-8f);
            float v1 = bessel_y1_fast(15.0f * r1) / (r1 + 1e-8f);
            g_tab[i] = make_float2(v0, v1 - v0);
        }
        return;
    }
    // ---- MLP blocks ----
    __shared__ float sW2[HID * HID], sW3[HID * HID], sW4[HID * HID];
    __shared__ float sW1[2 * HID], sW5[HID];
    __shared__ float sb1[HID], sb2[HID], sb3[HID], sb4[HID];
    __shared__ float sA[PTS_PER_BLK][HID], sB[PTS_PER_BLK][HID];

    int tid = threadIdx.x;
    for (int i = tid; i < HID * HID; i += 256) {
        sW2[i] = W2[i]; sW3[i] = W3[i]; sW4[i] = W4[i];
    }
    if (tid < 2 * HID) sW1[tid] = W1[tid];
    if (tid < HID) {
        sW5[tid] = W5[tid];
        sb1[tid] = b1[tid]; sb2[tid] = b2[tid];
        sb3[tid] = b3[tid]; sb4[tid] = b4[tid];
    }
    int p0 = blockIdx.x * PTS_PER_BLK;
    __syncthreads();

    for (int t = tid; t < PTS_PER_BLK * HID; t += 256) {
        int i = t / HID, j = t - i * HID;
        int gi = p0 + i;
        float x0 = bp[2 * gi], x1 = bp[2 * gi + 1];
        sA[i][j] = tanhf(fmaf(x0, sW1[j], fmaf(x1, sW1[HID + j], sb1[j])));
    }
    __syncthreads();
    for (int t = tid; t < PTS_PER_BLK * HID; t += 256) {
        int i = t / HID, j = t - i * HID;
        float acc = sb2[j];
        #pragma unroll
        for (int k = 0; k < HID; ++k) acc = fmaf(sA[i][k], sW2[k * HID + j], acc);
        sB[i][j] = tanhf(acc);
    }
    __syncthreads();
    for (int t = tid; t < PTS_PER_BLK * HID; t += 256) {
        int i = t / HID, j = t - i * HID;
        float acc = sb3[j];
        #pragma unroll
        for (int k = 0; k < HID; ++k) acc = fmaf(sB[i][k], sW3[k * HID + j], acc);
        sA[i][j] = tanhf(acc);
    }
    __syncthreads();
    for (int t = tid; t < PTS_PER_BLK * HID; t += 256) {
        int i = t / HID, j = t - i * HID;
        float acc = sb4[j];
        #pragma unroll
        for (int k = 0; k < HID; ++k) acc = fmaf(sA[i][k], sW4[k * HID + j], acc);
        sB[i][j] = tanhf(acc);
    }
    __syncthreads();
    for (int i = tid; i < PTS_PER_BLK; i += 256) {
        int gi = p0 + i;
        float acc = b5[0];
        #pragma unroll
        for (int k = 0; k < HID; ++k) acc = fmaf(sB[i][k], sW5[k], acc);
        int side = gi / Nside;
        float u = (side < 2) ? bp[2 * gi] : bp[2 * gi + 1];
        g_cord[gi] = u;
        g_h[gi] = acc;
    }
}

// ===================== fallback layered MLP (H != 50) =======================
__global__ void mlp_l1_kernel(const float* __restrict__ bp,
                              const float* __restrict__ W1,
                              const float* __restrict__ b1, int M, int H) {
    int idx = blockIdx.x * blockDim.x + threadIdx.x;
    if (idx >= M * H) return;
    int i = idx / H, j = idx - i * H;
    float v = fmaf(bp[2 * i + 1], W1[H + j], b1[j]);
    v = fmaf(bp[2 * i], W1[j], v);
    g_buf1[idx] = tanhf(v);
}
__global__ void mlp_mid_kernel(const float* __restrict__ W,
                               const float* __restrict__ b, int M, int H, int dir) {
    int idx = blockIdx.x * blockDim.x + threadIdx.x;
    if (idx >= M * H) return;
    int i = idx / H, j = idx - i * H;
    const float* in  = dir ? g_buf2 : g_buf1;
    float*       out = dir ? g_buf1 : g_buf2;
    float acc = b[j];
    const float* row = in + i * H;
    for (int k = 0; k < H; ++k) acc = fmaf(row[k], W[k * H + j], acc);
    out[idx] = tanhf(acc);
}
__global__ void mlp_out_kernel(const float* __restrict__ W5,
                               const float* __restrict__ b5,
                               const float* __restrict__ bp,
                               int M, int H, int Nside, int src) {
    int i = blockIdx.x * blockDim.x + threadIdx.x;
    if (i >= M) return;
    const float* in = src ? g_buf2 : g_buf1;
    float acc = b5[0];
    const float* row = in + i * H;
    for (int k = 0; k < H; ++k) acc = fmaf(row[k], W5[k], acc);
    int side = i / Nside;
    float u = (side < 2) ? bp[2 * i] : bp[2 * i + 1];
    g_cord[i] = u;
    g_h[i] = acc;
}

// ====================== exact near-field Y1 (x < 8) =========================
__device__ __forceinline__ float y1_small(float x, float invr) {
    float y = x * x;
    float jn = fmaf(y, -30.16036606f, 15704.48260f);
    jn = fmaf(y, jn, -2972611.439f); jn = fmaf(y, jn, 242396853.1f);
    jn = fmaf(y, jn, -7895059235.0f); jn = fmaf(y, jn, 72362614232.0f);
    jn *= x;
    float jd = y + 376.9991397f;
    jd = fmaf(y, jd, 99447.43394f); jd = fmaf(y, jd, 18583304.74f);
    jd = fmaf(y, jd, 2300535178.0f); jd = fmaf(y, jd, 144725228442.0f);
    float yn = fmaf(y, 8.511937935e4f, -4.237922726e7f);
    yn = fmaf(y, yn, 7.349264551e9f); yn = fmaf(y, yn, -5.153438139e11f);
    yn = fmaf(y, yn, 1.275274390e13f); yn = fmaf(y, yn, -4.900604943e13f);
    yn *= x;
    float yd = y + 3.549632885e3f;
    yd = fmaf(y, yd, 1.020426050e6f); yd = fmaf(y, yd, 2.245904002e8f);
    yd = fmaf(y, yd, 3.733650367e10f); yd = fmaf(y, yd, 4.244419664e12f);
    yd = fmaf(y, yd, 2.499580570e14f);
    float rden = rcpf(jd * yd);
    float j1 = jn * yd * rden;
    float ys = yn * jd * rden;
    float lg = __logf(x);
    float invx = invr * (1.0f / 15.0f);
    return fmaf(0.636619772f, fmaf(j1, lg, -invx), ys);
}

// LUT evaluation: G(r) ~ lerp(stab, r), magic-constant rounding, clamp-at-0.
__device__ __forceinline__ float lut_eval(float r2, const float2* __restrict__ stab) {
    float r = sqrt_apx(r2);
    float f = fmaxf(fmaf(r, SCALEf, OFFSf), 0.0f);
    float yb = f + MAGICf;
    int bits = __float_as_int(yb);
    float tr = yb - MAGICf;                 // round(f)
    float fa = f - tr;                      // in [-0.5, 0.5]
    float2 e = stab[bits & 0xFFF];
    return fmaf(fa, e.y, e.x);
}

// ============================ LUT main kernel ===============================
__global__ void __launch_bounds__(256, 4) bem_lut_kernel(
        const float* __restrict__ points,
        const float* __restrict__ dyp,
        float* __restrict__ out, int P, int Nside) {
    __shared__ __align__(16) float2 stab[TABN];
    for (int i = threadIdx.x; i < TABN; i += 256) stab[i] = g_tab[i];
    __syncthreads();

    int warp = (blockIdx.x * blockDim.x + threadIdx.x) >> 5;
    int lane = threadIdx.x & 31;
    if (warp >= P) return;

    float px = points[2 * warp];
    float py = points[2 * warp + 1];

    float a = g_cord[0];
    float step = (g_cord[Nside - 1] - a) * rcpf((float)(Nside - 1));
    float invstep = rcpf(step);
    float s32 = 32.0f * step, s64 = 64.0f * step, s96 = 96.0f * step;
    float s128 = 128.0f * step;

    float part = 0.0f;
    #pragma unroll
    for (int s = 0; s < 4; ++s) {
        float c = (s == 0) ? (py - 1.0f) : (s == 1) ? (-py)
                : (s == 2) ? (-px) : (px - 1.0f);
        float u = (s < 2) ? px : py;
        float d2 = c * c;
        int off = s * Nside;
        const float* hb = g_h + off;

        // ---- full branch-free LUT sweep (interleaved lane mapping) ----
        float acc0 = 0.0f, acc1 = 0.0f, acc2 = 0.0f, acc3 = 0.0f;
        float du = u - fmaf((float)lane, step, a);
        #pragma unroll 2
        for (int base = lane; base < Nside; base += 128) {
            float h0 = hb[base];
            float h1 = hb[base + 32];
            float h2 = hb[base + 64];
            float h3 = hb[base + 96];
            float duA = du;
            float duB = du - s32;
            float duC = du - s64;
            float duD = du - s96;
            float r2A = fmaf(duA, duA, d2);
            float r2B = fmaf(duB, duB, d2);
            float r2C = fmaf(duC, duC, d2);
            float r2D = fmaf(duD, duD, d2);
            acc0 = fmaf(lut_eval(r2A, stab), h0, acc0);
            acc1 = fmaf(lut_eval(r2B, stab), h1, acc1);
            acc2 = fmaf(lut_eval(r2C, stab), h2, acc2);
            acc3 = fmaf(lut_eval(r2D, stab), h3, acc3);
            du -= s128;
        }
        float acc = (acc0 + acc1) + (acc2 + acc3);

        // ---- near-field exact correction on analytic interval ----
        float t2 = RNEARf * RNEARf - d2;
        if (t2 > 0.0f) {
            float hw = sqrtf(t2);
            int jlo = (int)floorf((u - hw - a) * invstep);
            int jhi = (int)ceilf((u + hw - a) * invstep) + 1;
            jlo = max(jlo, 0); jhi = min(jhi, Nside);
            for (int j = jlo + lane; j < jhi; j += 32) {
                float cord = g_cord[off + j];
                float hval = hb[j];
                float duN = u - cord;
                float r2 = fmaf(duN, duN, d2);
                float r2g = fmaxf(r2, 1e-24f);
                float invr = rsqrtf(r2g);
                float r = r2g * invr;
                float invre = invr - 1e-8f * invr * invr;   // ~1/(r+eps)
                float exact = y1_small(15.0f * r, invr) * invre;
                float lutv = lut_eval(r2, stab);
                acc = fmaf(exact - lutv, hval, acc);
            }
        }
        part = fmaf(c, acc, part);
    }

    #pragma unroll
    for (int o = 16; o > 0; o >>= 1)
        part += __shfl_down_sync(0xffffffffu, part, o);
    if (lane == 0)
        out[warp] = 0.25f * 15.0f * dyp[0] * part;
}

// ================= scalar fallback main (general Nside) =====================
__device__ __forceinline__ float y1_eval_full(float x, float invr) {
    if (x < 8.0f) {
        return y1_small(x, invr);
    } else {
        float z = (8.0f / 15.0f) * invr;
        float y2 = z * z;
        float xx = x - 2.356194491f;
        float p1 = fmaf(y2, -0.240337019e-6f, 0.2457520174e-5f);
        p1 = fmaf(y2, p1, -0.3516396496e-4f); p1 = fmaf(y2, p1, 0.183105e-2f);
        p1 = fmaf(y2, p1, 1.0f);
        float p2 = fmaf(y2, 0.105787412e-6f, -0.88228987e-6f);
        p2 = fmaf(y2, p2, 0.8449199096e-5f); p2 = fmaf(y2, p2, -0.2002690873e-3f);
        p2 = fmaf(y2, p2, 0.04687499995f);
        float amp = rsqrtf(x * 1.5707963268f);
        float sn, cc;
        __sincosf(xx, &sn, &cc);
        return amp * fmaf(z, cc * p2, sn * p1);
    }
}
__global__ void __launch_bounds__(128) bem_main_scalar(
        const float* __restrict__ points, const float* __restrict__ dyp,
        float* __restrict__ out, int P, int Nside) {
    int gwarp = (blockIdx.x * blockDim.x + threadIdx.x) >> 5;
    int lane = threadIdx.x & 31;
    if (gwarp >= P) return;
    float px = points[2 * gwarp], py = points[2 * gwarp + 1];
    float part = 0.0f;
    #pragma unroll
    for (int s = 0; s < 4; ++s) {
        float c = (s == 0) ? (py - 1.0f) : (s == 1) ? (-py)
                : (s == 2) ? (-px) : (px - 1.0f);
        float u = (s < 2) ? px : py;
        float d2 = c * c;
        const float* gc = g_cord + s * Nside;
        const float* gh = g_h + s * Nside;
        float acc = 0.0f;
        for (int j = lane; j < Nside; j += 32) {
            float du = u - gc[j];
            float r2 = fmaxf(fmaf(du, du, d2), 1e-24f);
            float invr = rsqrtf(r2);
            float r = r2 * invr;
            float invre = invr - 1e-8f * invr * invr;
            acc = fmaf(y1_eval_full(15.0f * r, invr), gh[j] * invre, acc);
        }
        part = fmaf(c, acc, part);
    }
    #pragma unroll
    for (int o = 16; o > 0; o >>= 1)
        part += __shfl_down_sync(0xffffffffu, part, o);
    if (lane == 0) out[gwarp] = 0.25f * 15.0f * dyp[0] * part;
}

// ================================ launch ====================================
extern "C" void kernel_launch(void* const* d_in, const int* in_sizes, int n_in,
                              void* d_out, int out_size) {
    const float* points = (const float*)d_in[0];
    const float* bp     = (const float*)d_in[1];
    const float* dy     = (const float*)d_in[3];
    const float* W1 = (const float*)d_in[4];
    const float* b1 = (const float*)d_in[5];
    const float* W2 = (const float*)d_in[6];
    const float* b2 = (const float*)d_in[7];
    const float* W3 = (const float*)d_in[8];
    const float* b3 = (const float*)d_in[9];
    const float* W4 = (const float*)d_in[10];
    const float* b4 = (const float*)d_in[11];
    const float* W5 = (const float*)d_in[12];
    const float* b5 = (const float*)d_in[13];

    int P = in_sizes[0] / 2;
    int M = in_sizes[1] / 2;
    int H = in_sizes[5];
    int Nside = M / 4;

    if (H == HID && (M % PTS_PER_BLK) == 0) {
        int mlp_blocks = M / PTS_PER_BLK;
        prep_kernel<<<mlp_blocks + TAB_BLOCKS, 256>>>(
            bp, W1, b1, W2, b2, W3, b3, W4, b4, W5, b5, Nside, mlp_blocks);
    } else {
        // table still needed if LUT path taken
        prep_kernel<<<TAB_BLOCKS, 256>>>(bp, W1, b1, W2, b2, W3, b3, W4, b4,
                                         W5, b5, Nside, 0);
        int nh = M * H, tb = 256, gh = (nh + tb - 1) / tb;
        mlp_l1_kernel<<<gh, tb>>>(bp, W1, b1, M, H);
        mlp_mid_kernel<<<gh, tb>>>(W2, b2, M, H, 0);
        mlp_mid_kernel<<<gh, tb>>>(W3, b3, M, H, 1);
        mlp_mid_kernel<<<gh, tb>>>(W4, b4, M, H, 0);
        mlp_out_kernel<<<(M + tb - 1) / tb, tb>>>(W5, b5, bp, M, H, Nside, 1);
    }

    long long total = (long long)P * 32;
    if ((Nside % 128) == 0 && Nside >= 128) {
        int mb = 256;
        int mg = (int)((total + mb - 1) / mb);
        bem_lut_kernel<<<mg, mb>>>(points, dy, (float*)d_out, P, Nside);
    } else {
        int mb = 128;
        int mg = (int)((total + mb - 1) / mb);
        bem_main_scalar<<<mg, mb>>>(points, dy, (float*)d_out, P, Nside);
    }
}

// round 11
// speedup vs baseline: 3.0526x; 1.2427x over previous
#include <cuda_runtime.h>

// ---------------------------------------------------------------------------
// u[i] = 0.25*k*dy * sum_j Y1(k*r_ij) * (diff.n_j)/(r_ij+eps) * h_j
// Per side of unit square: diff.n = c_s (const per query), r^2=(u-cord)^2+c^2.
// G(r2) = Y1(15 sqrt(r2))/(sqrt(r2)+eps): LOG-SPACED shared LUT indexed by the
// float BIT PATTERN of r2 (256 steps/octave).  Entry stores (w,s) so that
// G ~ w + float(bits)*s  -> one FFMA, no sqrt, no fraction extraction.
// Near-field r < 2^-6 handled by exact (exact - lut) correction on an
// analytic contiguous j-interval (lut terms cancel exactly).
// ---------------------------------------------------------------------------

#define MAXM 4096
#define MAXH 64

#define HID 50
#define PTS_PER_BLK 32

#define SHIFTB  15
#define BIASu   29440u            // (115 << 23) >> 15 ;  2^-12 = r2 table start
#define TABN2   3336              // 13 octaves * 256 + pad
#define R2MINf  2.44140625e-4f    // 2^-12
#define RNEARf  0.0157f           // > 2^-6 = 0.015625
#define R2Nf    (RNEARf * RNEARf)

#define TAB_BLOCKS ((TABN2 + 255) / 256)

// scratch (no allocations allowed)
__device__ float  g_buf1[MAXM * MAXH];
__device__ float  g_buf2[MAXM * MAXH];
__device__ __align__(16) float g_cord[MAXM];
__device__ __align__(16) float g_h[MAXM];
__device__ __align__(16) float2 g_tab2[TABN2];

__device__ __forceinline__ float rcpf(float x) {
    float r; asm("rcp.approx.f32 %0,%1;" : "=f"(r) : "f"(x)); return r;
}

// ============== Y1 reference (table builder; fast intrinsics) ===============
__device__ float bessel_j1_fast(float x) {
    float ax = fabsf(x);
    if (ax < 8.0f) {
        float y = x * x;
        float num = x * (72362614232.0f + y * (-7895059235.0f + y * (242396853.1f +
                    y * (-2972611.439f + y * (15704.48260f + y * (-30.16036606f))))));
        float den = 144725228442.0f + y * (2300535178.0f + y * (18583304.74f +
                    y * (99447.43394f + y * (376.9991397f + y))));
        return num / den;
    } else {
        float z = 8.0f / ax;
        float y2 = z * z;
        float xx = ax - 2.356194491f;
        float p1 = 1.0f + y2 * (0.183105e-2f + y2 * (-0.3516396496e-4f +
                   y2 * (0.2457520174e-5f + y2 * (-0.240337019e-6f))));
        float p2 = 0.04687499995f + y2 * (-0.2002690873e-3f + y2 * (0.8449199096e-5f +
                   y2 * (-0.88228987e-6f + y2 * 0.105787412e-6f)));
        float v = sqrtf(0.636619772f / ax) * (__cosf(xx) * p1 - z * __sinf(xx) * p2);
        return (x < 0.0f) ? -v : v;
    }
}
__device__ float bessel_y1_fast(float x) {
    float xs = fmaxf(x, 1e-12f);
    if (xs < 8.0f) {
        float y = xs * xs;
        float num = xs * (-4.900604943e13f + y * (1.275274390e13f + y * (-5.153438139e11f +
                    y * (7.349264551e9f + y * (-4.237922726e7f + y * 8.511937935e4f)))));
        float den = 2.499580570e14f + y * (4.244419664e12f + y * (3.733650367e10f +
                    y * (2.245904002e8f + y * (1.020426050e6f + y * (3.549632885e3f + y)))));
        return num / den + 0.636619772f * (bessel_j1_fast(xs) * __logf(xs) - 1.0f / xs);
    } else {
        float z = 8.0f / xs;
        float y2 = z * z;
        float xx = xs - 2.356194491f;
        float p1 = 1.0f + y2 * (0.183105e-2f + y2 * (-0.3516396496e-4f +
                   y2 * (0.2457520174e-5f + y2 * (-0.240337019e-6f))));
        float p2 = 0.04687499995f + y2 * (-0.2002690873e-3f + y2 * (0.8449199096e-5f +
                   y2 * (-0.88228987e-6f + y2 * 0.105787412e-6f)));
        return sqrtf(0.636619772f / xs) * (__sinf(xx) * p1 + z * __cosf(xx) * p2);
    }
}

__device__ float eval_G_node(unsigned bits) {
    float r2 = __uint_as_float(bits);
    float r = sqrtf(r2);
    return bessel_y1_fast(15.0f * r) / (r + 1e-8f);
}

// =============== fused prep kernel: MLP blocks + table blocks ===============
__global__ void __launch_bounds__(256) prep_kernel(
        const float* __restrict__ bp,
        const float* __restrict__ W1, const float* __restrict__ b1,
        const float* __restrict__ W2, const float* __restrict__ b2,
        const float* __restrict__ W3, const float* __restrict__ b3,
        const float* __restrict__ W4, const float* __restrict__ b4,
        const float* __restrict__ W5, const float* __restrict__ b5,
        int Nside, int mlp_blocks) {
    if (blockIdx.x >= (unsigned)mlp_blocks) {
        // ---- table builder blocks: G ~ w + float(bits)*s per 2^15-bit cell
        int i = (blockIdx.x - mlp_blocks) * 256 + threadIdx.x;
        if (i < TABN2) {
            unsigned b0 = (BIASu + (unsigned)i) << SHIFTB;
            unsigned b1b = b0 + (1u << SHIFTB);
            double v0 = (double)eval_G_node(b0);
            double v1 = (double)eval_G_node(b1b);
            double s = (v1 - v0) / (double)(1u << SHIFTB);
            double w = v0 - (double)b0 * s;
            g_tab2[i] = make_float2((float)w, (float)s);
        }
        return;
    }
    // ---- MLP blocks ----
    __shared__ float sW2[HID * HID], sW3[HID * HID], sW4[HID * HID];
    __shared__ float sW1[2 * HID], sW5[HID];
    __shared__ float sb1[HID], sb2[HID], sb3[HID], sb4[HID];
    __shared__ float sA[PTS_PER_BLK][HID], sB[PTS_PER_BLK][HID];

    int tid = threadIdx.x;
    for (int i = tid; i < HID * HID; i += 256) {
        sW2[i] = W2[i]; sW3[i] = W3[i]; sW4[i] = W4[i];
    }
    if (tid < 2 * HID) sW1[tid] = W1[tid];
    if (tid < HID) {
        sW5[tid] = W5[tid];
        sb1[tid] = b1[tid]; sb2[tid] = b2[tid];
        sb3[tid] = b3[tid]; sb4[tid] = b4[tid];
    }
    int p0 = blockIdx.x * PTS_PER_BLK;
    __syncthreads();

    for (int t = tid; t < PTS_PER_BLK * HID; t += 256) {
        int i = t / HID, j = t - i * HID;
        int gi = p0 + i;
        float x0 = bp[2 * gi], x1 = bp[2 * gi + 1];
        sA[i][j] = tanhf(fmaf(x0, sW1[j], fmaf(x1, sW1[HID + j], sb1[j])));
    }
    __syncthreads();
    for (int t = tid; t < PTS_PER_BLK * HID; t += 256) {
        int i = t / HID, j = t - i * HID;
        float acc = sb2[j];
        #pragma unroll
        for (int k = 0; k < HID; ++k) acc = fmaf(sA[i][k], sW2[k * HID + j], acc);
        sB[i][j] = tanhf(acc);
    }
    __syncthreads();
    for (int t = tid; t < PTS_PER_BLK * HID; t += 256) {
        int i = t / HID, j = t - i * HID;
        float acc = sb3[j];
        #pragma unroll
        for (int k = 0; k < HID; ++k) acc = fmaf(sB[i][k], sW3[k * HID + j], acc);
        sA[i][j] = tanhf(acc);
    }
    __syncthreads();
    for (int t = tid; t < PTS_PER_BLK * HID; t += 256) {
        int i = t / HID, j = t - i * HID;
        float acc = sb4[j];
        #pragma unroll
        for (int k = 0; k < HID; ++k) acc = fmaf(sA[i][k], sW4[k * HID + j], acc);
        sB[i][j] = tanhf(acc);
    }
    __syncthreads();
    for (int i = tid; i < PTS_PER_BLK; i += 256) {
        int gi = p0 + i;
        float acc = b5[0];
        #pragma unroll
        for (int k = 0; k < HID; ++k) acc = fmaf(sB[i][k], sW5[k], acc);
        int side = gi / Nside;
        float u = (side < 2) ? bp[2 * gi] : bp[2 * gi + 1];
        g_cord[gi] = u;
        g_h[gi] = acc;
    }
}

// ===================== fallback layered MLP (H != 50) =======================
__global__ void mlp_l1_kernel(const float* __restrict__ bp,
                              const float* __restrict__ W1,
                              const float* __restrict__ b1, int M, int H) {
    int idx = blockIdx.x * blockDim.x + threadIdx.x;
    if (idx >= M * H) return;
    int i = idx / H, j = idx - i * H;
    float v = fmaf(bp[2 * i + 1], W1[H + j], b1[j]);
    v = fmaf(bp[2 * i], W1[j], v);
    g_buf1[idx] = tanhf(v);
}
__global__ void mlp_mid_kernel(const float* __restrict__ W,
                               const float* __restrict__ b, int M, int H, int dir) {
    int idx = blockIdx.x * blockDim.x + threadIdx.x;
    if (idx >= M * H) return;
    int i = idx / H, j = idx - i * H;
    const float* in  = dir ? g_buf2 : g_buf1;
    float*       out = dir ? g_buf1 : g_buf2;
    float acc = b[j];
    const float* row = in + i * H;
    for (int k = 0; k < H; ++k) acc = fmaf(row[k], W[k * H + j], acc);
    out[idx] = tanhf(acc);
}
__global__ void mlp_out_kernel(const float* __restrict__ W5,
                               const float* __restrict__ b5,
                               const float* __restrict__ bp,
                               int M, int H, int Nside, int src) {
    int i = blockIdx.x * blockDim.x + threadIdx.x;
    if (i >= M) return;
    const float* in = src ? g_buf2 : g_buf1;
    float acc = b5[0];
    const float* row = in + i * H;
    for (int k = 0; k < H; ++k) acc = fmaf(row[k], W5[k], acc);
    int side = i / Nside;
    float u = (side < 2) ? bp[2 * i] : bp[2 * i + 1];
    g_cord[i] = u;
    g_h[i] = acc;
}

// ====================== exact near-field Y1 (x < 8) =========================
__device__ __forceinline__ float y1_small(float x, float invr) {
    float y = x * x;
    float jn = fmaf(y, -30.16036606f, 15704.48260f);
    jn = fmaf(y, jn, -2972611.439f); jn = fmaf(y, jn, 242396853.1f);
    jn = fmaf(y, jn, -7895059235.0f); jn = fmaf(y, jn, 72362614232.0f);
    jn *= x;
    float jd = y + 376.9991397f;
    jd = fmaf(y, jd, 99447.43394f); jd = fmaf(y, jd, 18583304.74f);
    jd = fmaf(y, jd, 2300535178.0f); jd = fmaf(y, jd, 144725228442.0f);
    float yn = fmaf(y, 8.511937935e4f, -4.237922726e7f);
    yn = fmaf(y, yn, 7.349264551e9f); yn = fmaf(y, yn, -5.153438139e11f);
    yn = fmaf(y, yn, 1.275274390e13f); yn = fmaf(y, yn, -4.900604943e13f);
    yn *= x;
    float yd = y + 3.549632885e3f;
    yd = fmaf(y, yd, 1.020426050e6f); yd = fmaf(y, yd, 2.245904002e8f);
    yd = fmaf(y, yd, 3.733650367e10f); yd = fmaf(y, yd, 4.244419664e12f);
    yd = fmaf(y, yd, 2.499580570e14f);
    float rden = rcpf(jd * yd);
    float j1 = jn * yd * rden;
    float ys = yn * jd * rden;
    float lg = __logf(x);
    float invx = invr * (1.0f / 15.0f);
    return fmaf(0.636619772f, fmaf(j1, lg, -invx), ys);
}

// LUT: G(r2) ~ w + float(bits(r2)) * s  (log-spaced, 256 cells/octave)
__device__ __forceinline__ float lut_g(float r2, const float2* __restrict__ stab) {
    float r2c = fmaxf(r2, R2MINf);
    unsigned bits = __float_as_uint(r2c);
    float u = (float)(int)bits;                 // I2F (full-rate on alu/fma class)
    float2 e = stab[(bits >> SHIFTB) - BIASu];  // SHF + IMAD
    return fmaf(u, e.y, e.x);
}

// ============================ LUT main kernel ===============================
__global__ void __launch_bounds__(256) bem_lut_kernel(
        const float* __restrict__ points,
        const float* __restrict__ dyp,
        float* __restrict__ out, int P, int Nside) {
    __shared__ __align__(16) float2 stab[TABN2];
    for (int i = threadIdx.x; i < TABN2; i += 256) stab[i] = g_tab2[i];
    __syncthreads();

    int warp = (blockIdx.x * blockDim.x + threadIdx.x) >> 5;
    int lane = threadIdx.x & 31;
    if (warp >= P) return;

    float px = points[2 * warp];
    float py = points[2 * warp + 1];

    float a = g_cord[0];
    float step = (g_cord[Nside - 1] - a) * rcpf((float)(Nside - 1));
    float invstep = rcpf(step);
    float s32 = 32.0f * step, s64 = 64.0f * step, s96 = 96.0f * step;
    float s128 = 128.0f * step;

    float part = 0.0f;
    #pragma unroll
    for (int s = 0; s < 4; ++s) {
        float c = (s == 0) ? (py - 1.0f) : (s == 1) ? (-py)
                : (s == 2) ? (-px) : (px - 1.0f);
        float u = (s < 2) ? px : py;
        float d2 = c * c;
        int off = s * Nside;
        const float* hb = g_h + off + lane;

        // ---- full branch-free LUT sweep (interleaved lane mapping) ----
        float acc0 = 0.0f, acc1 = 0.0f, acc2 = 0.0f, acc3 = 0.0f;
        float du = u - fmaf((float)lane, step, a);
        int iters = Nside >> 7;                 // Nside / 128
        #pragma unroll 2
        for (int it = 0; it < iters; ++it) {
            float h0 = hb[0];
            float h1 = hb[32];
            float h2 = hb[64];
            float h3 = hb[96];
            float duB = du - s32;
            float duC = du - s64;
            float duD = du - s96;
            float r2A = fmaf(du,  du,  d2);
            float r2B = fmaf(duB, duB, d2);
            float r2C = fmaf(duC, duC, d2);
            float r2D = fmaf(duD, duD, d2);
            acc0 = fmaf(lut_g(r2A, stab), h0, acc0);
            acc1 = fmaf(lut_g(r2B, stab), h1, acc1);
            acc2 = fmaf(lut_g(r2C, stab), h2, acc2);
            acc3 = fmaf(lut_g(r2D, stab), h3, acc3);
            du -= s128;
            hb += 128;
        }
        float acc = (acc0 + acc1) + (acc2 + acc3);

        // ---- near-field exact correction on analytic interval ----
        float t2 = R2Nf - d2;
        if (t2 > 0.0f) {
            float hw = sqrtf(t2);
            int jlo = (int)floorf((u - hw - a) * invstep);
            int jhi = (int)ceilf((u + hw - a) * invstep) + 1;
            jlo = max(jlo, 0); jhi = min(jhi, Nside);
            for (int j = jlo + lane; j < jhi; j += 32) {
                float cord = g_cord[off + j];
                float hval = g_h[off + j];
                float duN = u - cord;
                float r2 = fmaf(duN, duN, d2);
                float r2g = fmaxf(r2, 1e-24f);
                float invr = rsqrtf(r2g);
                float r = r2g * invr;
                float invre = invr - 1e-8f * invr * invr;   // ~1/(r+eps)
                float exact = y1_small(15.0f * r, invr) * invre;
                float lutv = lut_g(r2, stab);
                acc = fmaf(exact - lutv, hval, acc);
            }
        }
        part = fmaf(c, acc, part);
    }

    #pragma unroll
    for (int o = 16; o > 0; o >>= 1)
        part += __shfl_down_sync(0xffffffffu, part, o);
    if (lane == 0)
        out[warp] = 0.25f * 15.0f * dyp[0] * part;
}

// ================= scalar fallback main (general Nside) =====================
__device__ __forceinline__ float y1_eval_full(float x, float invr) {
    if (x < 8.0f) {
        return y1_small(x, invr);
    } else {
        float z = (8.0f / 15.0f) * invr;
        float y2 = z * z;
        float xx = x - 2.356194491f;
        float p1 = fmaf(y2, -0.240337019e-6f, 0.2457520174e-5f);
        p1 = fmaf(y2, p1, -0.3516396496e-4f); p1 = fmaf(y2, p1, 0.183105e-2f);
        p1 = fmaf(y2, p1, 1.0f);
        float p2 = fmaf(y2, 0.105787412e-6f, -0.88228987e-6f);
        p2 = fmaf(y2, p2, 0.8449199096e-5f); p2 = fmaf(y2, p2, -0.2002690873e-3f);
        p2 = fmaf(y2, p2, 0.04687499995f);
        float amp = rsqrtf(x * 1.5707963268f);
        float sn, cc;
        __sincosf(xx, &sn, &cc);
        return amp * fmaf(z, cc * p2, sn * p1);
    }
}
__global__ void __launch_bounds__(128) bem_main_scalar(
        const float* __restrict__ points, const float* __restrict__ dyp,
        float* __restrict__ out, int P, int Nside) {
    int gwarp = (blockIdx.x * blockDim.x + threadIdx.x) >> 5;
    int lane = threadIdx.x & 31;
    if (gwarp >= P) return;
    float px = points[2 * gwarp], py = points[2 * gwarp + 1];
    float part = 0.0f;
    #pragma unroll
    for (int s = 0; s < 4; ++s) {
        float c = (s == 0) ? (py - 1.0f) : (s == 1) ? (-py)
                : (s == 2) ? (-px) : (px - 1.0f);
        float u = (s < 2) ? px : py;
        float d2 = c * c;
        const float* gc = g_cord + s * Nside;
        const float* gh = g_h + s * Nside;
        float acc = 0.0f;
        for (int j = lane; j < Nside; j += 32) {
            float du = u - gc[j];
            float r2 = fmaxf(fmaf(du, du, d2), 1e-24f);
            float invr = rsqrtf(r2);
            float r = r2 * invr;
            float invre = invr - 1e-8f * invr * invr;
            acc = fmaf(y1_eval_full(15.0f * r, invr), gh[j] * invre, acc);
        }
        part = fmaf(c, acc, part);
    }
    #pragma unroll
    for (int o = 16; o > 0; o >>= 1)
        part += __shfl_down_sync(0xffffffffu, part, o);
    if (lane == 0) out[gwarp] = 0.25f * 15.0f * dyp[0] * part;
}

// ================================ launch ====================================
extern "C" void kernel_launch(void* const* d_in, const int* in_sizes, int n_in,
                              void* d_out, int out_size) {
    const float* points = (const float*)d_in[0];
    const float* bp     = (const float*)d_in[1];
    const float* dy     = (const float*)d_in[3];
    const float* W1 = (const float*)d_in[4];
    const float* b1 = (const float*)d_in[5];
    const float* W2 = (const float*)d_in[6];
    const float* b2 = (const float*)d_in[7];
    const float* W3 = (const float*)d_in[8];
    const float* b3 = (const float*)d_in[9];
    const float* W4 = (const float*)d_in[10];
    const float* b4 = (const float*)d_in[11];
    const float* W5 = (const float*)d_in[12];
    const float* b5 = (const float*)d_in[13];

    int P = in_sizes[0] / 2;
    int M = in_sizes[1] / 2;
    int H = in_sizes[5];
    int Nside = M / 4;

    if (H == HID && (M % PTS_PER_BLK) == 0) {
        int mlp_blocks = M / PTS_PER_BLK;
        prep_kernel<<<mlp_blocks + TAB_BLOCKS, 256>>>(
            bp, W1, b1, W2, b2, W3, b3, W4, b4, W5, b5, Nside, mlp_blocks);
    } else {
        prep_kernel<<<TAB_BLOCKS, 256>>>(bp, W1, b1, W2, b2, W3, b3, W4, b4,
                                         W5, b5, Nside, 0);
        int nh = M * H, tb = 256, gh = (nh + tb - 1) / tb;
        mlp_l1_kernel<<<gh, tb>>>(bp, W1, b1, M, H);
        mlp_mid_kernel<<<gh, tb>>>(W2, b2, M, H, 0);
        mlp_mid_kernel<<<gh, tb>>>(W3, b3, M, H, 1);
        mlp_mid_kernel<<<gh, tb>>>(W4, b4, M, H, 0);
        mlp_out_kernel<<<(M + tb - 1) / tb, tb>>>(W5, b5, bp, M, H, Nside, 1);
    }

    long long total = (long long)P * 32;
    if ((Nside % 128) == 0 && Nside >= 128) {
        int mb = 256;
        int mg = (int)((total + mb - 1) / mb);
        bem_lut_kernel<<<mg, mb>>>(points, dy, (float*)d_out, P, Nside);
    } else {
        int mb = 128;
        int mg = (int)((total + mb - 1) / mb);
        bem_main_scalar<<<mg, mb>>>(points, dy, (float*)d_out, P, Nside);
    }
}

// round 16
// speedup vs baseline: 3.8069x; 1.2471x over previous
#include <cuda_runtime.h>

// ---------------------------------------------------------------------------
// u[i] = 0.25*k*dy * sum_j Y1(k*r_ij) * (diff.n_j)/(r_ij+eps) * h_j
// Per side: diff.n = c_s (const per query), r^2 = (u-cord_j)^2 + c_s^2.
// G(r2) = Y1(15 sqrt(r2))/(sqrt(r2)+eps): log-spaced shared LUT indexed by the
// float BIT PATTERN of r2 (256 cells/octave); entry (w,s): G ~ w + s*r2.
// PAIR DECIMATION: adjacent j share one midpoint LUT eval applied to
// hp = h0+h1 (first-order error cancels).  Near-field handled by exact
// (exact - lut_pair) correction on an analytic contiguous pair interval.
// ---------------------------------------------------------------------------

#define MAXM 4096
#define MAXH 64

#define HID 50
#define PTS_PER_BLK 32

#define SHIFTB  15
#define BIASu   29440u            // (115 << 23) >> 15 ;  2^-12 = r2 table start
#define TABN2   3336              // 13 octaves * 256 + pad
#define R2MINf  2.44140625e-4f    // 2^-12
#define RNEARf  0.0157f           // > 2^-6 = 0.015625
#define R2Nf    (RNEARf * RNEARf)

#define TAB_BLOCKS ((TABN2 + 255) / 256)

// scratch (no allocations allowed)
__device__ float  g_buf1[MAXM * MAXH];
__device__ float  g_buf2[MAXM * MAXH];
__device__ __align__(16) float g_cord[MAXM];
__device__ __align__(16) float g_h[MAXM];
__device__ __align__(16) float g_hp[MAXM / 2];   // pair sums h[2p]+h[2p+1]
__device__ __align__(16) float2 g_tab2[TABN2];

__device__ __forceinline__ float rcpf(float x) {
    float r; asm("rcp.approx.f32 %0,%1;" : "=f"(r) : "f"(x)); return r;
}

// ============== Y1 reference (table builder; fast intrinsics) ===============
__device__ float bessel_j1_fast(float x) {
    float ax = fabsf(x);
    if (ax < 8.0f) {
        float y = x * x;
        float num = x * (72362614232.0f + y * (-7895059235.0f + y * (242396853.1f +
                    y * (-2972611.439f + y * (15704.48260f + y * (-30.16036606f))))));
        float den = 144725228442.0f + y * (2300535178.0f + y * (18583304.74f +
                    y * (99447.43394f + y * (376.9991397f + y))));
        return num / den;
    } else {
        float z = 8.0f / ax;
        float y2 = z * z;
        float xx = ax - 2.356194491f;
        float p1 = 1.0f + y2 * (0.183105e-2f + y2 * (-0.3516396496e-4f +
                   y2 * (0.2457520174e-5f + y2 * (-0.240337019e-6f))));
        float p2 = 0.04687499995f + y2 * (-0.2002690873e-3f + y2 * (0.8449199096e-5f +
                   y2 * (-0.88228987e-6f + y2 * 0.105787412e-6f)));
        float v = sqrtf(0.636619772f / ax) * (__cosf(xx) * p1 - z * __sinf(xx) * p2);
        return (x < 0.0f) ? -v : v;
    }
}
__device__ float bessel_y1_fast(float x) {
    float xs = fmaxf(x, 1e-12f);
    if (xs < 8.0f) {
        float y = xs * xs;
        float num = xs * (-4.900604943e13f + y * (1.275274390e13f + y * (-5.153438139e11f +
                    y * (7.349264551e9f + y * (-4.237922726e7f + y * 8.511937935e4f)))));
        float den = 2.499580570e14f + y * (4.244419664e12f + y * (3.733650367e10f +
                    y * (2.245904002e8f + y * (1.020426050e6f + y * (3.549632885e3f + y)))));
        return num / den + 0.636619772f * (bessel_j1_fast(xs) * __logf(xs) - 1.0f / xs);
    } else {
        float z = 8.0f / xs;
        float y2 = z * z;
        float xx = xs - 2.356194491f;
        float p1 = 1.0f + y2 * (0.183105e-2f + y2 * (-0.3516396496e-4f +
                   y2 * (0.2457520174e-5f + y2 * (-0.240337019e-6f))));
        float p2 = 0.04687499995f + y2 * (-0.2002690873e-3f + y2 * (0.8449199096e-5f +
                   y2 * (-0.88228987e-6f + y2 * 0.105787412e-6f)));
        return sqrtf(0.636619772f / xs) * (__sinf(xx) * p1 + z * __cosf(xx) * p2);
    }
}

__device__ float eval_G_node(unsigned bits) {
    float r2 = __uint_as_float(bits);
    float r = sqrtf(r2);
    return bessel_y1_fast(15.0f * r) / (r + 1e-8f);
}

// =============== fused prep kernel: MLP blocks + table blocks ===============
__global__ void __launch_bounds__(256) prep_kernel(
        const float* __restrict__ bp,
        const float* __restrict__ W1, const float* __restrict__ b1,
        const float* __restrict__ W2, const float* __restrict__ b2,
        const float* __restrict__ W3, const float* __restrict__ b3,
        const float* __restrict__ W4, const float* __restrict__ b4,
        const float* __restrict__ W5, const float* __restrict__ b5,
        int Nside, int mlp_blocks) {
    if (blockIdx.x >= (unsigned)mlp_blocks) {
        // ---- table builder blocks: G ~ w + s*r2 per 2^15-bit cell (r2-affine)
        int i = (blockIdx.x - mlp_blocks) * 256 + threadIdx.x;
        if (i < TABN2) {
            unsigned b0 = (BIASu + (unsigned)i) << SHIFTB;
            unsigned b1b = b0 + (1u << SHIFTB);
            double v0 = (double)__uint_as_float(b0);
            double v1 = (double)__uint_as_float(b1b);
            double g0 = (double)eval_G_node(b0);
            double g1 = (double)eval_G_node(b1b);
            double s = (g1 - g0) / (v1 - v0);
            double w = g0 - v0 * s;
            g_tab2[i] = make_float2((float)w, (float)s);
        }
        return;
    }
    // ---- MLP blocks ----
    __shared__ float sW2[HID * HID], sW3[HID * HID], sW4[HID * HID];
    __shared__ float sW1[2 * HID], sW5[HID];
    __shared__ float sb1[HID], sb2[HID], sb3[HID], sb4[HID];
    __shared__ float sA[PTS_PER_BLK][HID], sB[PTS_PER_BLK][HID];

    int tid = threadIdx.x;
    for (int i = tid; i < HID * HID; i += 256) {
        sW2[i] = W2[i]; sW3[i] = W3[i]; sW4[i] = W4[i];
    }
    if (tid < 2 * HID) sW1[tid] = W1[tid];
    if (tid < HID) {
        sW5[tid] = W5[tid];
        sb1[tid] = b1[tid]; sb2[tid] = b2[tid];
        sb3[tid] = b3[tid]; sb4[tid] = b4[tid];
    }
    int p0 = blockIdx.x * PTS_PER_BLK;
    __syncthreads();

    for (int t = tid; t < PTS_PER_BLK * HID; t += 256) {
        int i = t / HID, j = t - i * HID;
        int gi = p0 + i;
        float x0 = bp[2 * gi], x1 = bp[2 * gi + 1];
        sA[i][j] = tanhf(fmaf(x0, sW1[j], fmaf(x1, sW1[HID + j], sb1[j])));
    }
    __syncthreads();
    for (int t = tid; t < PTS_PER_BLK * HID; t += 256) {
        int i = t / HID, j = t - i * HID;
        float acc = sb2[j];
        #pragma unroll
        for (int k = 0; k < HID; ++k) acc = fmaf(sA[i][k], sW2[k * HID + j], acc);
        sB[i][j] = tanhf(acc);
    }
    __syncthreads();
    for (int t = tid; t < PTS_PER_BLK * HID; t += 256) {
        int i = t / HID, j = t - i * HID;
        float acc = sb3[j];
        #pragma unroll
        for (int k = 0; k < HID; ++k) acc = fmaf(sB[i][k], sW3[k * HID + j], acc);
        sA[i][j] = tanhf(acc);
    }
    __syncthreads();
    for (int t = tid; t < PTS_PER_BLK * HID; t += 256) {
        int i = t / HID, j = t - i * HID;
        float acc = sb4[j];
        #pragma unroll
        for (int k = 0; k < HID; ++k) acc = fmaf(sA[i][k], sW4[k * HID + j], acc);
        sB[i][j] = tanhf(acc);
    }
    __syncthreads();
    // output (only warp 0: i = tid for tid < 32) + SoA store + pair sums
    for (int i = tid; i < PTS_PER_BLK; i += 256) {
        int gi = p0 + i;
        float acc = b5[0];
        #pragma unroll
        for (int k = 0; k < HID; ++k) acc = fmaf(sB[i][k], sW5[k], acc);
        int side = gi / Nside;
        float u = (side < 2) ? bp[2 * gi] : bp[2 * gi + 1];
        g_cord[gi] = u;
        g_h[gi] = acc;
        float hother = __shfl_xor_sync(0xffffffffu, acc, 1);
        if (!(i & 1)) g_hp[gi >> 1] = acc + hother;
    }
}

// ===================== fallback layered MLP (H != 50) =======================
__global__ void mlp_l1_kernel(const float* __restrict__ bp,
                              const float* __restrict__ W1,
                              const float* __restrict__ b1, int M, int H) {
    int idx = blockIdx.x * blockDim.x + threadIdx.x;
    if (idx >= M * H) return;
    int i = idx / H, j = idx - i * H;
    float v = fmaf(bp[2 * i + 1], W1[H + j], b1[j]);
    v = fmaf(bp[2 * i], W1[j], v);
    g_buf1[idx] = tanhf(v);
}
__global__ void mlp_mid_kernel(const float* __restrict__ W,
                               const float* __restrict__ b, int M, int H, int dir) {
    int idx = blockIdx.x * blockDim.x + threadIdx.x;
    if (idx >= M * H) return;
    int i = idx / H, j = idx - i * H;
    const float* in  = dir ? g_buf2 : g_buf1;
    float*       out = dir ? g_buf1 : g_buf2;
    float acc = b[j];
    const float* row = in + i * H;
    for (int k = 0; k < H; ++k) acc = fmaf(row[k], W[k * H + j], acc);
    out[idx] = tanhf(acc);
}
__global__ void mlp_out_kernel(const float* __restrict__ W5,
                               const float* __restrict__ b5,
                               const float* __restrict__ bp,
                               int M, int H, int Nside, int src) {
    int i = blockIdx.x * blockDim.x + threadIdx.x;
    if (i >= M) return;
    const float* in = src ? g_buf2 : g_buf1;
    float acc = b5[0];
    const float* row = in + i * H;
    for (int k = 0; k < H; ++k) acc = fmaf(row[k], W5[k], acc);
    int side = i / Nside;
    float u = (side < 2) ? bp[2 * i] : bp[2 * i + 1];
    g_cord[i] = u;
    g_h[i] = acc;
}
__global__ void hp_build_kernel(int Mhalf) {
    int p = blockIdx.x * blockDim.x + threadIdx.x;
    if (p < Mhalf) g_hp[p] = g_h[2 * p] + g_h[2 * p + 1];
}

// ====================== exact near-field Y1 (x < 8) =========================
__device__ __forceinline__ float y1_small(float x, float invr) {
    float y = x * x;
    float jn = fmaf(y, -30.16036606f, 15704.48260f);
    jn = fmaf(y, jn, -2972611.439f); jn = fmaf(y, jn, 242396853.1f);
    jn = fmaf(y, jn, -7895059235.0f); jn = fmaf(y, jn, 72362614232.0f);
    jn *= x;
    float jd = y + 376.9991397f;
    jd = fmaf(y, jd, 99447.43394f); jd = fmaf(y, jd, 18583304.74f);
    jd = fmaf(y, jd, 2300535178.0f); jd = fmaf(y, jd, 144725228442.0f);
    float yn = fmaf(y, 8.511937935e4f, -4.237922726e7f);
    yn = fmaf(y, yn, 7.349264551e9f); yn = fmaf(y, yn, -5.153438139e11f);
    yn = fmaf(y, yn, 1.275274390e13f); yn = fmaf(y, yn, -4.900604943e13f);
    yn *= x;
    float yd = y + 3.549632885e3f;
    yd = fmaf(y, yd, 1.020426050e6f); yd = fmaf(y, yd, 2.245904002e8f);
    yd = fmaf(y, yd, 3.733650367e10f); yd = fmaf(y, yd, 4.244419664e12f);
    yd = fmaf(y, yd, 2.499580570e14f);
    float rden = rcpf(jd * yd);
    float j1 = jn * yd * rden;
    float ys = yn * jd * rden;
    float lg = __logf(x);
    float invx = invr * (1.0f / 15.0f);
    return fmaf(0.636619772f, fmaf(j1, lg, -invx), ys);
}

// LUT: G(r2) ~ w + s*r2  (log-spaced cells, 256/octave, r2-affine entries)
__device__ __forceinline__ float lut_g(float r2, const float2* __restrict__ stab) {
    float r2c = fmaxf(r2, R2MINf);
    unsigned bits = __float_as_uint(r2c);
    float2 e = stab[(bits >> SHIFTB) - BIASu];  // SHF + IMAD
    return fmaf(r2c, e.y, e.x);
}

// ============================ LUT main kernel ===============================
// Pair decimation: one LUT eval at the pair midpoint serves h[2p]+h[2p+1].
__global__ void __launch_bounds__(256) bem_lut_kernel(
        const float* __restrict__ points,
        const float* __restrict__ dyp,
        float* __restrict__ out, int P, int Nside) {
    __shared__ __align__(16) float2 stab[TABN2];
    for (int i = threadIdx.x; i < TABN2; i += 256) stab[i] = g_tab2[i];
    __syncthreads();

    int warp = (blockIdx.x * blockDim.x + threadIdx.x) >> 5;
    int lane = threadIdx.x & 31;
    if (warp >= P) return;

    float px = points[2 * warp];
    float py = points[2 * warp + 1];

    int Np = Nside >> 1;
    float a = g_cord[0];
    float step = (g_cord[Nside - 1] - a) * rcpf((float)(Nside - 1));
    float invstep = rcpf(step);
    float t64 = 64.0f * step, t128 = 128.0f * step, t192 = 192.0f * step;
    float t256 = 256.0f * step;

    float part = 0.0f;
    #pragma unroll
    for (int s = 0; s < 4; ++s) {
        float c = (s == 0) ? (py - 1.0f) : (s == 1) ? (-py)
                : (s == 2) ? (-px) : (px - 1.0f);
        float u = (s < 2) ? px : py;
        float d2 = c * c;
        int off = s * Nside;
        int poff = s * Np;
        const float* hb = g_hp + poff + lane;

        // ---- full branch-free LUT sweep over PAIRS (interleaved lanes) ----
        float acc0 = 0.0f, acc1 = 0.0f, acc2 = 0.0f, acc3 = 0.0f;
        // pair p midpoint cord = a + (2p + 0.5)*step ; initial p = lane
        float du = u - fmaf(2.0f * (float)lane + 0.5f, step, a);
        int iters = Np >> 7;                   // Np / 128
        #pragma unroll 2
        for (int it = 0; it < iters; ++it) {
            float h0 = hb[0];
            float h1 = hb[32];
            float h2 = hb[64];
            float h3 = hb[96];
            float duB = du - t64;
            float duC = du - t128;
            float duD = du - t192;
            float r2A = fmaf(du,  du,  d2);
            float r2B = fmaf(duB, duB, d2);
            float r2C = fmaf(duC, duC, d2);
            float r2D = fmaf(duD, duD, d2);
            acc0 = fmaf(lut_g(r2A, stab), h0, acc0);
            acc1 = fmaf(lut_g(r2B, stab), h1, acc1);
            acc2 = fmaf(lut_g(r2C, stab), h2, acc2);
            acc3 = fmaf(lut_g(r2D, stab), h3, acc3);
            du -= t256;
            hb += 128;
        }
        float acc = (acc0 + acc1) + (acc2 + acc3);

        // ---- near-field exact correction on analytic PAIR interval ----
        float t2 = R2Nf - d2;
        if (t2 > 0.0f) {
            float hw = sqrtf(t2);
            int jlo = (int)floorf((u - hw - a) * invstep);
            int jhi = (int)ceilf((u + hw - a) * invstep) + 1;
            jlo = max(jlo, 0); jhi = min(jhi, Nside);
            jlo &= ~1;                          // even-align to pairs
            jhi = (jhi + 1) & ~1;
            if (jhi > Nside) jhi = Nside;
            if (jhi < jlo) jhi = jlo;
            int plo = jlo >> 1, phi = jhi >> 1;
            for (int p = plo + lane; p < phi; p += 32) {
                int j0 = 2 * p;
                float c0 = g_cord[off + j0];
                float c1 = g_cord[off + j0 + 1];
                float h0v = g_h[off + j0];
                float h1v = g_h[off + j0 + 1];
                float hpv = g_hp[poff + p];
                // exact both elements
                float du0 = u - c0;
                float r20 = fmaxf(fmaf(du0, du0, d2), 1e-24f);
                float i0 = rsqrtf(r20);
                float r0 = r20 * i0;
                float ie0 = i0 - 1e-8f * i0 * i0;
                float e0 = y1_small(15.0f * r0, i0) * ie0;
                float du1 = u - c1;
                float r21 = fmaxf(fmaf(du1, du1, d2), 1e-24f);
                float i1 = rsqrtf(r21);
                float r1 = r21 * i1;
                float ie1 = i1 - 1e-8f * i1 * i1;
                float e1 = y1_small(15.0f * r1, i1) * ie1;
                // subtract the sweep's pair term (analytic midpoint)
                float dum = u - fmaf(2.0f * (float)p + 0.5f, step, a);
                float r2m = fmaf(dum, dum, d2);
                float lutv = lut_g(r2m, stab);
                acc += fmaf(e0, h0v, fmaf(e1, h1v, -lutv * hpv));
            }
        }
        part = fmaf(c, acc, part);
    }

    #pragma unroll
    for (int o = 16; o > 0; o >>= 1)
        part += __shfl_down_sync(0xffffffffu, part, o);
    if (lane == 0)
        out[warp] = 0.25f * 15.0f * dyp[0] * part;
}

// ================= scalar fallback main (general Nside) =====================
__device__ __forceinline__ float y1_eval_full(float x, float invr) {
    if (x < 8.0f) {
        return y1_small(x, invr);
    } else {
        float z = (8.0f / 15.0f) * invr;
        float y2 = z * z;
        float xx = x - 2.356194491f;
        float p1 = fmaf(y2, -0.240337019e-6f, 0.2457520174e-5f);
        p1 = fmaf(y2, p1, -0.3516396496e-4f); p1 = fmaf(y2, p1, 0.183105e-2f);
        p1 = fmaf(y2, p1, 1.0f);
        float p2 = fmaf(y2, 0.105787412e-6f, -0.88228987e-6f);
        p2 = fmaf(y2, p2, 0.8449199096e-5f); p2 = fmaf(y2, p2, -0.2002690873e-3f);
        p2 = fmaf(y2, p2, 0.04687499995f);
        float amp = rsqrtf(x * 1.5707963268f);
        float sn, cc;
        __sincosf(xx, &sn, &cc);
        return amp * fmaf(z, cc * p2, sn * p1);
    }
}
__global__ void __launch_bounds__(128) bem_main_scalar(
        const float* __restrict__ points, const float* __restrict__ dyp,
        float* __restrict__ out, int P, int Nside) {
    int gwarp = (blockIdx.x * blockDim.x + threadIdx.x) >> 5;
    int lane = threadIdx.x & 31;
    if (gwarp >= P) return;
    float px = points[2 * gwarp], py = points[2 * gwarp + 1];
    float part = 0.0f;
    #pragma unroll
    for (int s = 0; s < 4; ++s) {
        float c = (s == 0) ? (py - 1.0f) : (s == 1) ? (-py)
                : (s == 2) ? (-px) : (px - 1.0f);
        float u = (s < 2) ? px : py;
        float d2 = c * c;
        const float* gc = g_cord + s * Nside;
        const float* gh = g_h + s * Nside;
        float acc = 0.0f;
        for (int j = lane; j < Nside; j += 32) {
            float du = u - gc[j];
            float r2 = fmaxf(fmaf(du, du, d2), 1e-24f);
            float invr = rsqrtf(r2);
            float r = r2 * invr;
            float invre = invr - 1e-8f * invr * invr;
            acc = fmaf(y1_eval_full(15.0f * r, invr), gh[j] * invre, acc);
        }
        part = fmaf(c, acc, part);
    }
    #pragma unroll
    for (int o = 16; o > 0; o >>= 1)
        part += __shfl_down_sync(0xffffffffu, part, o);
    if (lane == 0) out[gwarp] = 0.25f * 15.0f * dyp[0] * part;
}

// ================================ launch ====================================
extern "C" void kernel_launch(void* const* d_in, const int* in_sizes, int n_in,
                              void* d_out, int out_size) {
    const float* points = (const float*)d_in[0];
    const float* bp     = (const float*)d_in[1];
    const float* dy     = (const float*)d_in[3];
    const float* W1 = (const float*)d_in[4];
    const float* b1 = (const float*)d_in[5];
    const float* W2 = (const float*)d_in[6];
    const float* b2 = (const float*)d_in[7];
    const float* W3 = (const float*)d_in[8];
    const float* b3 = (const float*)d_in[9];
    const float* W4 = (const float*)d_in[10];
    const float* b4 = (const float*)d_in[11];
    const float* W5 = (const float*)d_in[12];
    const float* b5 = (const float*)d_in[13];

    int P = in_sizes[0] / 2;
    int M = in_sizes[1] / 2;
    int H = in_sizes[5];
    int Nside = M / 4;

    bool lut_path = ((Nside % 256) == 0 && Nside >= 256);

    if (H == HID && (M % PTS_PER_BLK) == 0) {
        int mlp_blocks = M / PTS_PER_BLK;
        prep_kernel<<<mlp_blocks + TAB_BLOCKS, 256>>>(
            bp, W1, b1, W2, b2, W3, b3, W4, b4, W5, b5, Nside, mlp_blocks);
    } else {
        prep_kernel<<<TAB_BLOCKS, 256>>>(bp, W1, b1, W2, b2, W3, b3, W4, b4,
                                         W5, b5, Nside, 0);
        int nh = M * H, tb = 256, gh = (nh + tb - 1) / tb;
        mlp_l1_kernel<<<gh, tb>>>(bp, W1, b1, M, H);
        mlp_mid_kernel<<<gh, tb>>>(W2, b2, M, H, 0);
        mlp_mid_kernel<<<gh, tb>>>(W3, b3, M, H, 1);
        mlp_mid_kernel<<<gh, tb>>>(W4, b4, M, H, 0);
        mlp_out_kernel<<<(M + tb - 1) / tb, tb>>>(W5, b5, bp, M, H, Nside, 1);
        if (lut_path)
            hp_build_kernel<<<(M / 2 + 255) / 256, 256>>>(M / 2);
    }

    long long total = (long long)P * 32;
    if (lut_path) {
        int mb = 256;
        int mg = (int)((total + mb - 1) / mb);
        bem_lut_kernel<<<mg, mb>>>(points, dy, (float*)d_out, P, Nside);
    } else {
        int mb = 128;
        int mg = (int)((total + mb - 1) / mb);
        bem_main_scalar<<<mg, mb>>>(points, dy, (float*)d_out, P, Nside);
    }
}